// round 12
// baseline (speedup 1.0000x reference)
#include <cuda_runtime.h>
#include <cuda_bf16.h>
#include <math.h>
#include <cstdint>
#include <cstddef>

#define T_TOK 8192
#define D_IN  1024
#define DFF   4096
#define NE    8

// ---------------- device scratch (ONLY referenced inside kernels) -----------
__device__ int   g_count[NE];
__device__ int   g_slot[NE * T_TOK];
__device__ float g_scale[T_TOK];

__device__ __align__(16) __nv_bfloat16 g_x_hi[(size_t)T_TOK * D_IN];
__device__ __align__(16) __nv_bfloat16 g_x_lo[(size_t)T_TOK * D_IN];
__device__ __align__(16) __nv_bfloat16 g_h_hi[(size_t)T_TOK * DFF];      // token-indexed
__device__ __align__(16) __nv_bfloat16 g_h_lo[(size_t)T_TOK * DFF];
__device__ __align__(16) __nv_bfloat16 g_w1_hi[(size_t)NE * D_IN * DFF]; // [E][K][N] native
__device__ __align__(16) __nv_bfloat16 g_w1_lo[(size_t)NE * D_IN * DFF];
__device__ __align__(16) __nv_bfloat16 g_w2_hi[(size_t)NE * DFF * D_IN];
__device__ __align__(16) __nv_bfloat16 g_w2_lo[(size_t)NE * DFF * D_IN];

// ---------------- PTX helpers ----------------
__device__ __forceinline__ unsigned smem_u32(const void* p) {
    unsigned a;
    asm("{ .reg .u64 t; cvta.to.shared.u64 t, %1; cvt.u32.u64 %0, t; }" : "=r"(a) : "l"(p));
    return a;
}
#define LDSM_X4(r, a) \
    asm volatile("ldmatrix.sync.aligned.m8n8.x4.shared.b16 {%0,%1,%2,%3}, [%4];" \
        : "=r"((r)[0]), "=r"((r)[1]), "=r"((r)[2]), "=r"((r)[3]) : "r"(a))
#define LDSM_X4_T(r, a) \
    asm volatile("ldmatrix.sync.aligned.m8n8.x4.trans.shared.b16 {%0,%1,%2,%3}, [%4];" \
        : "=r"((r)[0]), "=r"((r)[1]), "=r"((r)[2]), "=r"((r)[3]) : "r"(a))
#define MMA_BF16(d, a, b0, b1) \
    asm volatile("mma.sync.aligned.m16n8k16.row.col.f32.bf16.bf16.f32 " \
        "{%0,%1,%2,%3}, {%4,%5,%6,%7}, {%8,%9}, {%0,%1,%2,%3};" \
        : "+f"((d)[0]), "+f"((d)[1]), "+f"((d)[2]), "+f"((d)[3]) \
        : "r"((a)[0]), "r"((a)[1]), "r"((a)[2]), "r"((a)[3]), "r"(b0), "r"(b1))

// ---------------- misc helpers ----------------
__device__ __forceinline__ float gelu_exact(float v) {
    return 0.5f * v * (1.0f + erff(v * 0.70710678118654752f));
}
__device__ __forceinline__ unsigned pack_bf2(float a, float b) {
    __nv_bfloat162 t = __floats2bfloat162_rn(a, b);
    return reinterpret_cast<unsigned&>(t);
}

// ---------------- kernel 0: zero counters ----------------
__global__ void zero_counts_k() { if (threadIdx.x < NE) g_count[threadIdx.x] = 0; }

// ---------------- kernel 1: router (proven) ----------------
__global__ void router_k(const float* __restrict__ x, const float* __restrict__ gw) {
    int warp = (blockIdx.x * blockDim.x + threadIdx.x) >> 5;
    int lane = threadIdx.x & 31;
    if (warp >= T_TOK) return;
    const float* xr = x + (size_t)warp * D_IN;
    double acc[NE];
#pragma unroll
    for (int j = 0; j < NE; j++) acc[j] = 0.0;
    for (int d = lane; d < D_IN; d += 32) {
        float xv = xr[d];
        const float4* g4 = reinterpret_cast<const float4*>(gw + d * NE);
        float4 a = g4[0], b = g4[1];
        acc[0] += (double)xv * a.x; acc[1] += (double)xv * a.y;
        acc[2] += (double)xv * a.z; acc[3] += (double)xv * a.w;
        acc[4] += (double)xv * b.x; acc[5] += (double)xv * b.y;
        acc[6] += (double)xv * b.z; acc[7] += (double)xv * b.w;
    }
#pragma unroll
    for (int j = 0; j < NE; j++)
#pragma unroll
        for (int s = 16; s > 0; s >>= 1)
            acc[j] += __shfl_xor_sync(0xffffffffu, acc[j], s);
    if (lane == 0) {
        double m = acc[0]; int am = 0;
#pragma unroll
        for (int j = 1; j < NE; j++) if (acc[j] > m) { m = acc[j]; am = j; }
        double s = 0.0;
#pragma unroll
        for (int j = 0; j < NE; j++) s += exp(acc[j] - m);
        g_scale[warp] = (float)(1.0 / s);
        int pos = atomicAdd(&g_count[am], 1);
        g_slot[am * T_TOK + pos] = warp;
    }
}

// ---------------- elementwise hi/lo split; targets selected IN-KERNEL -------
template <int SEL>   // 0: x planes, 1: w1 planes, 2: w2 planes
__global__ void split_sel_k(const float* __restrict__ in) {
    __nv_bfloat16* hi = (SEL == 0) ? g_x_hi : (SEL == 1) ? g_w1_hi : g_w2_hi;
    __nv_bfloat16* lo = (SEL == 0) ? g_x_lo : (SEL == 1) ? g_w1_lo : g_w2_lo;
    size_t i = (size_t)blockIdx.x * blockDim.x + threadIdx.x;
    float4 v = reinterpret_cast<const float4*>(in)[i];
    float f[4] = {v.x, v.y, v.z, v.w}, l[4];
#pragma unroll
    for (int q = 0; q < 4; q++) {
        float h = __bfloat162float(__float2bfloat16_rn(f[q]));
        l[q] = f[q] - h;
    }
    reinterpret_cast<uint2*>(hi)[i] = make_uint2(pack_bf2(f[0], f[1]), pack_bf2(f[2], f[3]));
    reinterpret_cast<uint2*>(lo)[i] = make_uint2(pack_bf2(l[0], l[1]), pack_bf2(l[2], l[3]));
}

// ---------------- grouped GEMM: raw mma, k-step 32, 2x32KB dynamic smem -----
// Block 128x128, 8 warps (wm = wid&1, wn = wid>>1). R7 fragment math.
// Stage (32 KB): Ahi 8K | Alo 8K | Bhi 8K | Blo 8K.
//   A plane: 128 rows x 64B (32 k), 16B chunk q stored at q ^ ((row>>1)&3).
//   B plane: 32 krows x 256B (128 n), 16B chunk nc stored at nc ^ (krow&7).
// ONE __syncthreads per 32-k step; next-stage LDG/STS interleaved per 16-k half.
template <bool DO_GELU>
__global__ __launch_bounds__(256, 2)
void moe_mma(const float* __restrict__ Bias, float* __restrict__ OutF,
             int K, int N) {
    const int e  = blockIdx.z;
    const int Me = g_count[e];
    const int m0 = blockIdx.y * 128;
    if (m0 >= Me) return;
    const int n0 = blockIdx.x * 128;

    const __nv_bfloat16* Ahi = DO_GELU ? g_x_hi : g_h_hi;
    const __nv_bfloat16* Alo = DO_GELU ? g_x_lo : g_h_lo;
    const __nv_bfloat16* Whi = DO_GELU ? g_w1_hi : g_w2_hi;
    const __nv_bfloat16* Wlo = DO_GELU ? g_w1_lo : g_w2_lo;

    extern __shared__ __align__(16) unsigned char sm[];   // 2 x 32768
    __shared__ int toks[128];

    const int tid = threadIdx.x;
    if (tid < 128) {
        int p = m0 + tid;
        toks[tid] = (p < Me) ? g_slot[e * T_TOK + p] : -1;
    }
    __syncthreads();

    // A staging: thread -> (row ar, within-half chunk aq); zero rows for pads
    const int ar = tid >> 1;
    const int aq = tid & 1;
    const int tokA = toks[ar];
    const __nv_bfloat16* aph = (tokA >= 0) ? (Ahi + (size_t)tokA * K + aq * 8) : nullptr;
    const __nv_bfloat16* apl = (tokA >= 0) ? (Alo + (size_t)tokA * K + aq * 8) : nullptr;
    const int aswz = (ar >> 1) & 3;
    // per-half STS offsets: chunk = 2h + aq
    const unsigned aoff0 = (unsigned)(ar * 64 + (((0 + aq) ^ aswz) << 4));
    const unsigned aoff1 = (unsigned)(ar * 64 + (((2 + aq) ^ aswz) << 4));
    // B staging: thread -> (krow-in-half bk, n-chunk bnc)
    const int bk  = tid >> 4;
    const int bnc = tid & 15;
    const size_t bbase = ((size_t)e * K + bk) * N + n0 + bnc * 8;  // + krow_g*N
    const unsigned boff = (unsigned)(16384 + bk * 256 + ((bnc ^ (bk & 7)) << 4)); // +h*4096

    const int wid = tid >> 5, lane = tid & 31;
    const int wm = wid & 1, wn = wid >> 1;
    const int lane4 = lane & 15, laneh = lane >> 4;
    const int fswz = (lane4 >> 1) & 3;
    // A fragment offsets per kc: rows wm*64 + mi*16 + lane4, 64B stride
    const unsigned offA0 = (unsigned)((wm * 64 + lane4) * 64 + (((0 + laneh) ^ fswz) << 4));
    const unsigned offA1 = (unsigned)((wm * 64 + lane4) * 64 + (((2 + laneh) ^ fswz) << 4));
    const int khalf = (lane >> 4) & 1, ngrp = (lane >> 3) & 1, tt = lane & 7;
    const int krow = khalf * 8 + tt;  // within 16-k group; kc adds 16 rows = 4096B
    const unsigned offB0 = (unsigned)(16384 + krow * 256 + (((wn * 4 + ngrp)     ^ tt) << 4));
    const unsigned offB1 = (unsigned)(16384 + krow * 256 + (((wn * 4 + 2 + ngrp) ^ tt) << 4));
    const unsigned base = smem_u32(sm);

    float acc[4][4][4];
#pragma unroll
    for (int i = 0; i < 4; i++)
#pragma unroll
        for (int j = 0; j < 4; j++)
#pragma unroll
            for (int q = 0; q < 4; q++) acc[i][j][q] = 0.0f;

    // prologue: stage 0 <- k in [0, 32)
#pragma unroll
    for (int h = 0; h < 2; h++) {
        uint4 pah = make_uint4(0u, 0u, 0u, 0u), pal = pah;
        if (aph) {
            pah = *reinterpret_cast<const uint4*>(aph + h * 16);
            pal = *reinterpret_cast<const uint4*>(apl + h * 16);
        }
        uint4 pbh = *reinterpret_cast<const uint4*>(Whi + bbase + (size_t)(h * 16) * N);
        uint4 pbl = *reinterpret_cast<const uint4*>(Wlo + bbase + (size_t)(h * 16) * N);
        *reinterpret_cast<uint4*>(sm + ((h == 0) ? aoff0 : aoff1))        = pah;
        *reinterpret_cast<uint4*>(sm + 8192 + ((h == 0) ? aoff0 : aoff1)) = pal;
        *reinterpret_cast<uint4*>(sm + boff + h * 4096)                   = pbh;
        *reinterpret_cast<uint4*>(sm + 8192 + boff + h * 4096)            = pbl;
    }
    __syncthreads();

    const int KS = K / 32;
    for (int i = 0; i < KS; i++) {
        const unsigned sb = base + (i & 1) * 32768;
        unsigned char* sn = sm + ((i + 1) & 1) * 32768;
        const bool more = (i + 1 < KS);
        const int kk = (i + 1) * 32;

        unsigned ah[4][4], al[4][4], bh[2][4], bl[2][4];
        // ---- kc = 0 ----
#pragma unroll
        for (int mi = 0; mi < 4; mi++) {
            LDSM_X4(ah[mi], sb + offA0 + mi * 1024);
            LDSM_X4(al[mi], sb + 8192 + offA0 + mi * 1024);
        }
        LDSM_X4_T(bh[0], sb + offB0);
        LDSM_X4_T(bh[1], sb + offB1);
        LDSM_X4_T(bl[0], sb + 8192 + offB0);
        LDSM_X4_T(bl[1], sb + 8192 + offB1);

        uint4 pah, pal, pbh, pbl;
        if (more) {   // next-stage half 0 LDGs land behind kc0 MMAs
            pah = make_uint4(0u, 0u, 0u, 0u); pal = pah;
            if (aph) {
                pah = *reinterpret_cast<const uint4*>(aph + kk);
                pal = *reinterpret_cast<const uint4*>(apl + kk);
            }
            pbh = *reinterpret_cast<const uint4*>(Whi + bbase + (size_t)kk * N);
            pbl = *reinterpret_cast<const uint4*>(Wlo + bbase + (size_t)kk * N);
        }
#pragma unroll
        for (int mi = 0; mi < 4; mi++)
#pragma unroll
            for (int nt = 0; nt < 4; nt++) {
                const int nj = nt >> 1, sel = nt & 1;
                MMA_BF16(acc[mi][nt], ah[mi], bh[nj][sel], bh[nj][sel + 2]);
                MMA_BF16(acc[mi][nt], ah[mi], bl[nj][sel], bl[nj][sel + 2]);
                MMA_BF16(acc[mi][nt], al[mi], bh[nj][sel], bh[nj][sel + 2]);
            }
        if (more) {
            *reinterpret_cast<uint4*>(sn + aoff0)        = pah;
            *reinterpret_cast<uint4*>(sn + 8192 + aoff0) = pal;
            *reinterpret_cast<uint4*>(sn + boff)         = pbh;
            *reinterpret_cast<uint4*>(sn + 8192 + boff)  = pbl;
        }

        // ---- kc = 1 ----
#pragma unroll
        for (int mi = 0; mi < 4; mi++) {
            LDSM_X4(ah[mi], sb + offA1 + mi * 1024);
            LDSM_X4(al[mi], sb + 8192 + offA1 + mi * 1024);
        }
        LDSM_X4_T(bh[0], sb + offB0 + 4096);
        LDSM_X4_T(bh[1], sb + offB1 + 4096);
        LDSM_X4_T(bl[0], sb + 8192 + offB0 + 4096);
        LDSM_X4_T(bl[1], sb + 8192 + offB1 + 4096);

        if (more) {   // next-stage half 1
            pah = make_uint4(0u, 0u, 0u, 0u); pal = pah;
            if (aph) {
                pah = *reinterpret_cast<const uint4*>(aph + kk + 16);
                pal = *reinterpret_cast<const uint4*>(apl + kk + 16);
            }
            pbh = *reinterpret_cast<const uint4*>(Whi + bbase + (size_t)(kk + 16) * N);
            pbl = *reinterpret_cast<const uint4*>(Wlo + bbase + (size_t)(kk + 16) * N);
        }
#pragma unroll
        for (int mi = 0; mi < 4; mi++)
#pragma unroll
            for (int nt = 0; nt < 4; nt++) {
                const int nj = nt >> 1, sel = nt & 1;
                MMA_BF16(acc[mi][nt], ah[mi], bh[nj][sel], bh[nj][sel + 2]);
                MMA_BF16(acc[mi][nt], ah[mi], bl[nj][sel], bl[nj][sel + 2]);
                MMA_BF16(acc[mi][nt], al[mi], bh[nj][sel], bh[nj][sel + 2]);
            }
        if (more) {
            *reinterpret_cast<uint4*>(sn + aoff1)               = pah;
            *reinterpret_cast<uint4*>(sn + 8192 + aoff1)        = pal;
            *reinterpret_cast<uint4*>(sn + boff + 4096)         = pbh;
            *reinterpret_cast<uint4*>(sn + 8192 + boff + 4096)  = pbl;
        }
        __syncthreads();
    }

    // ---------------- epilogue (R7 mapping) ----------------
    // acc[mi][nt]: d0=(r0,c), d1=(r0,c+1), d2=(r0+8,c), d3=(r0+8,c+1)
    float bb[4][2];
#pragma unroll
    for (int nt = 0; nt < 4; nt++) {
        const float2 bv = *reinterpret_cast<const float2*>(
            Bias + (size_t)e * N + n0 + wn * 32 + nt * 8 + (lane & 3) * 2);
        bb[nt][0] = bv.x; bb[nt][1] = bv.y;
    }

#pragma unroll
    for (int mi = 0; mi < 4; mi++) {
        const int r0 = wm * 64 + mi * 16 + (lane >> 2);
        const int t0 = toks[r0], t1 = toks[r0 + 8];
        if (DO_GELU) {
#pragma unroll
            for (int nt = 0; nt < 4; nt++) {
                const int col = n0 + wn * 32 + nt * 8 + (lane & 3) * 2;
                if (t0 >= 0) {
                    float v0 = gelu_exact(acc[mi][nt][0] + bb[nt][0]);
                    float v1 = gelu_exact(acc[mi][nt][1] + bb[nt][1]);
                    float h0 = __bfloat162float(__float2bfloat16_rn(v0));
                    float h1 = __bfloat162float(__float2bfloat16_rn(v1));
                    *reinterpret_cast<unsigned*>(g_h_hi + (size_t)t0 * N + col) = pack_bf2(v0, v1);
                    *reinterpret_cast<unsigned*>(g_h_lo + (size_t)t0 * N + col) = pack_bf2(v0 - h0, v1 - h1);
                }
                if (t1 >= 0) {
                    float v2 = gelu_exact(acc[mi][nt][2] + bb[nt][0]);
                    float v3 = gelu_exact(acc[mi][nt][3] + bb[nt][1]);
                    float h2 = __bfloat162float(__float2bfloat16_rn(v2));
                    float h3 = __bfloat162float(__float2bfloat16_rn(v3));
                    *reinterpret_cast<unsigned*>(g_h_hi + (size_t)t1 * N + col) = pack_bf2(v2, v3);
                    *reinterpret_cast<unsigned*>(g_h_lo + (size_t)t1 * N + col) = pack_bf2(v2 - h2, v3 - h3);
                }
            }
        } else {
            const float s0 = (t0 >= 0) ? g_scale[t0] : 0.0f;
            const float s1 = (t1 >= 0) ? g_scale[t1] : 0.0f;
#pragma unroll
            for (int nt = 0; nt < 4; nt++) {
                const int col = n0 + wn * 32 + nt * 8 + (lane & 3) * 2;
                if (t0 >= 0) {
                    float2 v = make_float2((acc[mi][nt][0] + bb[nt][0]) * s0,
                                           (acc[mi][nt][1] + bb[nt][1]) * s0);
                    *reinterpret_cast<float2*>(OutF + (size_t)t0 * N + col) = v;
                }
                if (t1 >= 0) {
                    float2 v = make_float2((acc[mi][nt][2] + bb[nt][0]) * s1,
                                           (acc[mi][nt][3] + bb[nt][1]) * s1);
                    *reinterpret_cast<float2*>(OutF + (size_t)t1 * N + col) = v;
                }
            }
        }
    }
}

#define SMEM_DYN 65536

// ---------------- launch ----------------
extern "C" void kernel_launch(void* const* d_in, const int* in_sizes, int n_in,
                              void* d_out, int out_size) {
    const float* x  = (const float*)d_in[0];
    const float* gw = (const float*)d_in[1];
    const float* w1 = (const float*)d_in[2];
    const float* b1 = (const float*)d_in[3];
    const float* w2 = (const float*)d_in[4];
    const float* b2 = (const float*)d_in[5];
    float* out = (float*)d_out;

    // unconditional (deterministic, capture-safe): opt in to 64 KB dynamic smem
    cudaFuncSetAttribute(moe_mma<true>,  cudaFuncAttributeMaxDynamicSharedMemorySize, SMEM_DYN);
    cudaFuncSetAttribute(moe_mma<false>, cudaFuncAttributeMaxDynamicSharedMemorySize, SMEM_DYN);

    zero_counts_k<<<1, 32>>>();
    router_k<<<(T_TOK * 32) / 256, 256>>>(x, gw);

    split_sel_k<0><<<((size_t)T_TOK * D_IN / 4) / 256, 256>>>(x);
    split_sel_k<1><<<((size_t)NE * D_IN * DFF / 4) / 256, 256>>>(w1);
    split_sel_k<2><<<((size_t)NE * DFF * D_IN / 4) / 256, 256>>>(w2);

    dim3 g1(DFF / 128, T_TOK / 128, NE);   // empty m-tiles early-exit
    moe_mma<true><<<g1, 256, SMEM_DYN>>>(b1, nullptr, D_IN, DFF);

    dim3 g2(D_IN / 128, T_TOK / 128, NE);
    moe_mma<false><<<g2, 256, SMEM_DYN>>>(b2, out, DFF, D_IN);
}

// round 13
// speedup vs baseline: 1.4079x; 1.4079x over previous
#include <cuda_runtime.h>
#include <cuda_bf16.h>
#include <math.h>
#include <cstdint>
#include <cstddef>

#define T_TOK 8192
#define D_IN  1024
#define DFF   4096
#define NE    8

// ---------------- device scratch (ONLY referenced inside kernels) -----------
__device__ int   g_count[NE];
__device__ int   g_slot[NE * T_TOK];
__device__ float g_scale[T_TOK];

__device__ __align__(16) __nv_bfloat16 g_x_hi[(size_t)T_TOK * D_IN];
__device__ __align__(16) __nv_bfloat16 g_x_lo[(size_t)T_TOK * D_IN];
__device__ __align__(16) __nv_bfloat16 g_h_hi[(size_t)T_TOK * DFF];      // token-indexed
__device__ __align__(16) __nv_bfloat16 g_h_lo[(size_t)T_TOK * DFF];
__device__ __align__(16) __nv_bfloat16 g_w1_hi[(size_t)NE * D_IN * DFF]; // [E][K][N] native
__device__ __align__(16) __nv_bfloat16 g_w1_lo[(size_t)NE * D_IN * DFF];
__device__ __align__(16) __nv_bfloat16 g_w2_hi[(size_t)NE * DFF * D_IN];
__device__ __align__(16) __nv_bfloat16 g_w2_lo[(size_t)NE * DFF * D_IN];

// ---------------- PTX helpers ----------------
__device__ __forceinline__ unsigned smem_u32(const void* p) {
    unsigned a;
    asm("{ .reg .u64 t; cvta.to.shared.u64 t, %1; cvt.u32.u64 %0, t; }" : "=r"(a) : "l"(p));
    return a;
}
#define LDSM_X4(r, a) \
    asm volatile("ldmatrix.sync.aligned.m8n8.x4.shared.b16 {%0,%1,%2,%3}, [%4];" \
        : "=r"((r)[0]), "=r"((r)[1]), "=r"((r)[2]), "=r"((r)[3]) : "r"(a))
#define LDSM_X4_T(r, a) \
    asm volatile("ldmatrix.sync.aligned.m8n8.x4.trans.shared.b16 {%0,%1,%2,%3}, [%4];" \
        : "=r"((r)[0]), "=r"((r)[1]), "=r"((r)[2]), "=r"((r)[3]) : "r"(a))
#define MMA_BF16(d, a, b0, b1) \
    asm volatile("mma.sync.aligned.m16n8k16.row.col.f32.bf16.bf16.f32 " \
        "{%0,%1,%2,%3}, {%4,%5,%6,%7}, {%8,%9}, {%0,%1,%2,%3};" \
        : "+f"((d)[0]), "+f"((d)[1]), "+f"((d)[2]), "+f"((d)[3]) \
        : "r"((a)[0]), "r"((a)[1]), "r"((a)[2]), "r"((a)[3]), "r"(b0), "r"(b1))

// ---------------- misc helpers ----------------
__device__ __forceinline__ float gelu_exact(float v) {
    return 0.5f * v * (1.0f + erff(v * 0.70710678118654752f));
}
__device__ __forceinline__ unsigned pack_bf2(float a, float b) {
    __nv_bfloat162 t = __floats2bfloat162_rn(a, b);
    return reinterpret_cast<unsigned&>(t);
}

// ---------------- kernel 0: zero counters ----------------
__global__ void zero_counts_k() { if (threadIdx.x < NE) g_count[threadIdx.x] = 0; }

// ---------------- kernel 1: router (proven) ----------------
__global__ void router_k(const float* __restrict__ x, const float* __restrict__ gw) {
    int warp = (blockIdx.x * blockDim.x + threadIdx.x) >> 5;
    int lane = threadIdx.x & 31;
    if (warp >= T_TOK) return;
    const float* xr = x + (size_t)warp * D_IN;
    double acc[NE];
#pragma unroll
    for (int j = 0; j < NE; j++) acc[j] = 0.0;
    for (int d = lane; d < D_IN; d += 32) {
        float xv = xr[d];
        const float4* g4 = reinterpret_cast<const float4*>(gw + d * NE);
        float4 a = g4[0], b = g4[1];
        acc[0] += (double)xv * a.x; acc[1] += (double)xv * a.y;
        acc[2] += (double)xv * a.z; acc[3] += (double)xv * a.w;
        acc[4] += (double)xv * b.x; acc[5] += (double)xv * b.y;
        acc[6] += (double)xv * b.z; acc[7] += (double)xv * b.w;
    }
#pragma unroll
    for (int j = 0; j < NE; j++)
#pragma unroll
        for (int s = 16; s > 0; s >>= 1)
            acc[j] += __shfl_xor_sync(0xffffffffu, acc[j], s);
    if (lane == 0) {
        double m = acc[0]; int am = 0;
#pragma unroll
        for (int j = 1; j < NE; j++) if (acc[j] > m) { m = acc[j]; am = j; }
        double s = 0.0;
#pragma unroll
        for (int j = 0; j < NE; j++) s += exp(acc[j] - m);
        g_scale[warp] = (float)(1.0 / s);
        int pos = atomicAdd(&g_count[am], 1);
        g_slot[am * T_TOK + pos] = warp;
    }
}

// ---------------- elementwise hi/lo split; targets selected IN-KERNEL -------
template <int SEL>   // 0: x planes, 1: w1 planes, 2: w2 planes
__global__ void split_sel_k(const float* __restrict__ in) {
    __nv_bfloat16* hi = (SEL == 0) ? g_x_hi : (SEL == 1) ? g_w1_hi : g_w2_hi;
    __nv_bfloat16* lo = (SEL == 0) ? g_x_lo : (SEL == 1) ? g_w1_lo : g_w2_lo;
    size_t i = (size_t)blockIdx.x * blockDim.x + threadIdx.x;
    float4 v = reinterpret_cast<const float4*>(in)[i];
    float f[4] = {v.x, v.y, v.z, v.w}, l[4];
#pragma unroll
    for (int q = 0; q < 4; q++) {
        float h = __bfloat162float(__float2bfloat16_rn(f[q]));
        l[q] = f[q] - h;
    }
    reinterpret_cast<uint2*>(hi)[i] = make_uint2(pack_bf2(f[0], f[1]), pack_bf2(f[2], f[3]));
    reinterpret_cast<uint2*>(lo)[i] = make_uint2(pack_bf2(l[0], l[1]), pack_bf2(l[2], l[3]));
}

// ---------------- grouped GEMM: raw mma, 3-stage smem pipeline --------------
// Block 128x128, k-step 16, 8 warps (wm = wid&1, wn = wid>>1). R7 fragment math.
// Three 16 KB stages: Ahi 4K | Alo 4K | Bhi 4K | Blo 4K each. One sync/k-step.
// Schedule at step i: STS(held regs -> stage (i+1)%3), LDG(k_{i+2} -> regs),
// LDSM+MMA on stage i%3, sync. LDG gets ~2 k-steps to land.
// A swizzle: chunk c ^= (row>>2)&1.  B swizzle: n-chunk nc ^= krow&7.
template <bool DO_GELU>
__global__ __launch_bounds__(256, 2)
void moe_mma(const float* __restrict__ Bias, float* __restrict__ OutF,
             int K, int N) {
    const int e  = blockIdx.z;
    const int Me = g_count[e];
    const int m0 = blockIdx.y * 128;
    if (m0 >= Me) return;
    const int n0 = blockIdx.x * 128;

    const __nv_bfloat16* Ahi = DO_GELU ? g_x_hi : g_h_hi;
    const __nv_bfloat16* Alo = DO_GELU ? g_x_lo : g_h_lo;
    const __nv_bfloat16* Whi = DO_GELU ? g_w1_hi : g_w2_hi;
    const __nv_bfloat16* Wlo = DO_GELU ? g_w1_lo : g_w2_lo;

    __shared__ __align__(16) unsigned char sm[3][16384];
    __shared__ int toks[128];

    const int tid = threadIdx.x;
    if (tid < 128) {
        int p = m0 + tid;
        toks[tid] = (p < Me) ? g_slot[e * T_TOK + p] : -1;
    }
    __syncthreads();

    // A staging: thread -> (row ar, 16B chunk ac8 of the 32B row)
    const int ar  = tid >> 1;
    const int ac8 = tid & 1;
    const int tokA = toks[ar];
    const __nv_bfloat16* aph = (tokA >= 0) ? (Ahi + (size_t)tokA * K + ac8 * 8) : nullptr;
    const __nv_bfloat16* apl = (tokA >= 0) ? (Alo + (size_t)tokA * K + ac8 * 8) : nullptr;
    const unsigned aoff = (unsigned)(ar * 32 + ((ac8 ^ ((ar >> 2) & 1)) << 4));
    // B staging: thread -> (k-row bk, n-chunk bnc)
    const int bk  = tid >> 4;
    const int bnc = tid & 15;
    const size_t bbase = ((size_t)e * K + bk) * N + n0 + bnc * 8;
    const unsigned boff = (unsigned)(bk * 256 + ((bnc ^ (bk & 7)) << 4));

    const int wid = tid >> 5, lane = tid & 31;
    const int wm = wid & 1, wn = wid >> 1;
    const int lane4 = lane & 15, laneh = lane >> 4;
    const unsigned offA = (unsigned)((wm * 64 + lane4) * 32 + ((laneh ^ ((lane4 >> 2) & 1)) << 4));
    const int khalf = (lane >> 4) & 1, ngrp = (lane >> 3) & 1, tt = lane & 7;
    const int krow = khalf * 8 + tt;
    const unsigned offB0 = (unsigned)(8192 + krow * 256 + (((wn * 4 + ngrp)     ^ (krow & 7)) << 4));
    const unsigned offB1 = (unsigned)(8192 + krow * 256 + (((wn * 4 + 2 + ngrp) ^ (krow & 7)) << 4));
    const unsigned base = smem_u32(sm);

    float acc[4][4][4];
#pragma unroll
    for (int i = 0; i < 4; i++)
#pragma unroll
        for (int j = 0; j < 4; j++)
#pragma unroll
            for (int q = 0; q < 4; q++) acc[i][j][q] = 0.0f;

    // prologue: stage0 <- k=0 (direct); regs <- k=16 (held)
    uint4 pah = make_uint4(0u, 0u, 0u, 0u), pal = pah, pbh, pbl;
    {
        uint4 t0 = pah, t1 = pah;
        if (aph) {
            t0 = *reinterpret_cast<const uint4*>(aph);
            t1 = *reinterpret_cast<const uint4*>(apl);
        }
        uint4 t2 = *reinterpret_cast<const uint4*>(Whi + bbase);
        uint4 t3 = *reinterpret_cast<const uint4*>(Wlo + bbase);
        unsigned char* s0 = (unsigned char*)sm;
        *reinterpret_cast<uint4*>(s0 + aoff)          = t0;
        *reinterpret_cast<uint4*>(s0 + 4096  + aoff)  = t1;
        *reinterpret_cast<uint4*>(s0 + 8192  + boff)  = t2;
        *reinterpret_cast<uint4*>(s0 + 12288 + boff)  = t3;
    }
    if (16 < K) {
        if (aph) {
            pah = *reinterpret_cast<const uint4*>(aph + 16);
            pal = *reinterpret_cast<const uint4*>(apl + 16);
        }
        pbh = *reinterpret_cast<const uint4*>(Whi + bbase + (size_t)16 * N);
        pbl = *reinterpret_cast<const uint4*>(Wlo + bbase + (size_t)16 * N);
    }
    __syncthreads();

    const int KS = K / 16;
    int s_cur = 0;
    for (int i = 0; i < KS; i++) {
        // 1) STS held regs (k_{i+1}) into stage (i+1)%3
        if (i + 1 < KS) {
            int s_nxt = s_cur + 1; if (s_nxt == 3) s_nxt = 0;
            unsigned char* sn = (unsigned char*)sm + s_nxt * 16384;
            *reinterpret_cast<uint4*>(sn + aoff)          = pah;
            *reinterpret_cast<uint4*>(sn + 4096  + aoff)  = pal;
            *reinterpret_cast<uint4*>(sn + 8192  + boff)  = pbh;
            *reinterpret_cast<uint4*>(sn + 12288 + boff)  = pbl;
        }
        // 2) LDG k_{i+2} into regs (2 k-steps to land)
        const int k2 = (i + 2) * 16;
        if (k2 < K) {
            if (aph) {
                pah = *reinterpret_cast<const uint4*>(aph + k2);
                pal = *reinterpret_cast<const uint4*>(apl + k2);
            } else {
                pah = make_uint4(0u, 0u, 0u, 0u); pal = pah;
            }
            pbh = *reinterpret_cast<const uint4*>(Whi + bbase + (size_t)k2 * N);
            pbl = *reinterpret_cast<const uint4*>(Wlo + bbase + (size_t)k2 * N);
        }

        // 3) LDSM + MMA on stage s_cur
        const unsigned sb = base + s_cur * 16384;
        unsigned ah[4][4], al[4][4], bh[2][4], bl[2][4];
#pragma unroll
        for (int mi = 0; mi < 4; mi++) {
            LDSM_X4(ah[mi], sb + offA + mi * 512);
            LDSM_X4(al[mi], sb + 4096 + offA + mi * 512);
        }
        LDSM_X4_T(bh[0], sb + offB0);
        LDSM_X4_T(bh[1], sb + offB1);
        LDSM_X4_T(bl[0], sb + offB0 + 4096);
        LDSM_X4_T(bl[1], sb + offB1 + 4096);

#pragma unroll
        for (int mi = 0; mi < 4; mi++)
#pragma unroll
            for (int nt = 0; nt < 4; nt++) {
                const int nj = nt >> 1, sel = nt & 1;
                MMA_BF16(acc[mi][nt], ah[mi], bh[nj][sel], bh[nj][sel + 2]);
                MMA_BF16(acc[mi][nt], ah[mi], bl[nj][sel], bl[nj][sel + 2]);
                MMA_BF16(acc[mi][nt], al[mi], bh[nj][sel], bh[nj][sel + 2]);
            }

        if (++s_cur == 3) s_cur = 0;
        __syncthreads();
    }

    // ---------------- epilogue (R7 mapping) ----------------
    // acc[mi][nt]: d0=(r0,c), d1=(r0,c+1), d2=(r0+8,c), d3=(r0+8,c+1)
    float bb[4][2];
#pragma unroll
    for (int nt = 0; nt < 4; nt++) {
        const float2 bv = *reinterpret_cast<const float2*>(
            Bias + (size_t)e * N + n0 + wn * 32 + nt * 8 + (lane & 3) * 2);
        bb[nt][0] = bv.x; bb[nt][1] = bv.y;
    }

#pragma unroll
    for (int mi = 0; mi < 4; mi++) {
        const int r0 = wm * 64 + mi * 16 + (lane >> 2);
        const int t0 = toks[r0], t1 = toks[r0 + 8];
        if (DO_GELU) {
#pragma unroll
            for (int nt = 0; nt < 4; nt++) {
                const int col = n0 + wn * 32 + nt * 8 + (lane & 3) * 2;
                if (t0 >= 0) {
                    float v0 = gelu_exact(acc[mi][nt][0] + bb[nt][0]);
                    float v1 = gelu_exact(acc[mi][nt][1] + bb[nt][1]);
                    float h0 = __bfloat162float(__float2bfloat16_rn(v0));
                    float h1 = __bfloat162float(__float2bfloat16_rn(v1));
                    *reinterpret_cast<unsigned*>(g_h_hi + (size_t)t0 * N + col) = pack_bf2(v0, v1);
                    *reinterpret_cast<unsigned*>(g_h_lo + (size_t)t0 * N + col) = pack_bf2(v0 - h0, v1 - h1);
                }
                if (t1 >= 0) {
                    float v2 = gelu_exact(acc[mi][nt][2] + bb[nt][0]);
                    float v3 = gelu_exact(acc[mi][nt][3] + bb[nt][1]);
                    float h2 = __bfloat162float(__float2bfloat16_rn(v2));
                    float h3 = __bfloat162float(__float2bfloat16_rn(v3));
                    *reinterpret_cast<unsigned*>(g_h_hi + (size_t)t1 * N + col) = pack_bf2(v2, v3);
                    *reinterpret_cast<unsigned*>(g_h_lo + (size_t)t1 * N + col) = pack_bf2(v2 - h2, v3 - h3);
                }
            }
        } else {
            const float s0 = (t0 >= 0) ? g_scale[t0] : 0.0f;
            const float s1 = (t1 >= 0) ? g_scale[t1] : 0.0f;
#pragma unroll
            for (int nt = 0; nt < 4; nt++) {
                const int col = n0 + wn * 32 + nt * 8 + (lane & 3) * 2;
                if (t0 >= 0) {
                    float2 v = make_float2((acc[mi][nt][0] + bb[nt][0]) * s0,
                                           (acc[mi][nt][1] + bb[nt][1]) * s0);
                    *reinterpret_cast<float2*>(OutF + (size_t)t0 * N + col) = v;
                }
                if (t1 >= 0) {
                    float2 v = make_float2((acc[mi][nt][2] + bb[nt][0]) * s1,
                                           (acc[mi][nt][3] + bb[nt][1]) * s1);
                    *reinterpret_cast<float2*>(OutF + (size_t)t1 * N + col) = v;
                }
            }
        }
    }
}

// ---------------- launch ----------------
extern "C" void kernel_launch(void* const* d_in, const int* in_sizes, int n_in,
                              void* d_out, int out_size) {
    const float* x  = (const float*)d_in[0];
    const float* gw = (const float*)d_in[1];
    const float* w1 = (const float*)d_in[2];
    const float* b1 = (const float*)d_in[3];
    const float* w2 = (const float*)d_in[4];
    const float* b2 = (const float*)d_in[5];
    float* out = (float*)d_out;

    zero_counts_k<<<1, 32>>>();
    router_k<<<(T_TOK * 32) / 256, 256>>>(x, gw);

    split_sel_k<0><<<((size_t)T_TOK * D_IN / 4) / 256, 256>>>(x);
    split_sel_k<1><<<((size_t)NE * D_IN * DFF / 4) / 256, 256>>>(w1);
    split_sel_k<2><<<((size_t)NE * DFF * D_IN / 4) / 256, 256>>>(w2);

    dim3 g1(DFF / 128, T_TOK / 128, NE);   // empty m-tiles early-exit
    moe_mma<true><<<g1, 256>>>(b1, nullptr, D_IN, DFF);

    dim3 g2(D_IN / 128, T_TOK / 128, NE);
    moe_mma<false><<<g2, 256>>>(b2, out, DFF, D_IN);
}

// round 14
// speedup vs baseline: 1.4481x; 1.0286x over previous
#include <cuda_runtime.h>
#include <cuda_bf16.h>
#include <math.h>
#include <cstdint>
#include <cstddef>

#define T_TOK 8192
#define D_IN  1024
#define DFF   4096
#define NE    8

// ---------------- device scratch (ONLY referenced inside kernels) -----------
__device__ int   g_count[NE];
__device__ int   g_slot[NE * T_TOK];
__device__ float g_scale[T_TOK];

__device__ __align__(16) __nv_bfloat16 g_x_hi[(size_t)T_TOK * D_IN];
__device__ __align__(16) __nv_bfloat16 g_x_lo[(size_t)T_TOK * D_IN];
__device__ __align__(16) __nv_bfloat16 g_h_hi[(size_t)T_TOK * DFF];      // token-indexed
__device__ __align__(16) __nv_bfloat16 g_h_lo[(size_t)T_TOK * DFF];
__device__ __align__(16) __nv_bfloat16 g_w1_hi[(size_t)NE * D_IN * DFF]; // [E][K][N] native
__device__ __align__(16) __nv_bfloat16 g_w1_lo[(size_t)NE * D_IN * DFF];
__device__ __align__(16) __nv_bfloat16 g_w2_hi[(size_t)NE * DFF * D_IN];
__device__ __align__(16) __nv_bfloat16 g_w2_lo[(size_t)NE * DFF * D_IN];

// ---------------- PTX helpers ----------------
__device__ __forceinline__ unsigned smem_u32(const void* p) {
    unsigned a;
    asm("{ .reg .u64 t; cvta.to.shared.u64 t, %1; cvt.u32.u64 %0, t; }" : "=r"(a) : "l"(p));
    return a;
}
#define LDSM_X4(r, a) \
    asm volatile("ldmatrix.sync.aligned.m8n8.x4.shared.b16 {%0,%1,%2,%3}, [%4];" \
        : "=r"((r)[0]), "=r"((r)[1]), "=r"((r)[2]), "=r"((r)[3]) : "r"(a))
#define LDSM_X4_T(r, a) \
    asm volatile("ldmatrix.sync.aligned.m8n8.x4.trans.shared.b16 {%0,%1,%2,%3}, [%4];" \
        : "=r"((r)[0]), "=r"((r)[1]), "=r"((r)[2]), "=r"((r)[3]) : "r"(a))
#define MMA_BF16(d, a, b0, b1) \
    asm volatile("mma.sync.aligned.m16n8k16.row.col.f32.bf16.bf16.f32 " \
        "{%0,%1,%2,%3}, {%4,%5,%6,%7}, {%8,%9}, {%0,%1,%2,%3};" \
        : "+f"((d)[0]), "+f"((d)[1]), "+f"((d)[2]), "+f"((d)[3]) \
        : "r"((a)[0]), "r"((a)[1]), "r"((a)[2]), "r"((a)[3]), "r"(b0), "r"(b1))

// ---------------- misc helpers ----------------
__device__ __forceinline__ float gelu_exact(float v) {
    return 0.5f * v * (1.0f + erff(v * 0.70710678118654752f));
}
__device__ __forceinline__ unsigned pack_bf2(float a, float b) {
    __nv_bfloat162 t = __floats2bfloat162_rn(a, b);
    return reinterpret_cast<unsigned&>(t);
}

// ---------------- kernel 0: zero counters ----------------
__global__ void zero_counts_k() { if (threadIdx.x < NE) g_count[threadIdx.x] = 0; }

// ---------------- kernel 1: router (proven) ----------------
__global__ void router_k(const float* __restrict__ x, const float* __restrict__ gw) {
    int warp = (blockIdx.x * blockDim.x + threadIdx.x) >> 5;
    int lane = threadIdx.x & 31;
    if (warp >= T_TOK) return;
    const float* xr = x + (size_t)warp * D_IN;
    double acc[NE];
#pragma unroll
    for (int j = 0; j < NE; j++) acc[j] = 0.0;
    for (int d = lane; d < D_IN; d += 32) {
        float xv = xr[d];
        const float4* g4 = reinterpret_cast<const float4*>(gw + d * NE);
        float4 a = g4[0], b = g4[1];
        acc[0] += (double)xv * a.x; acc[1] += (double)xv * a.y;
        acc[2] += (double)xv * a.z; acc[3] += (double)xv * a.w;
        acc[4] += (double)xv * b.x; acc[5] += (double)xv * b.y;
        acc[6] += (double)xv * b.z; acc[7] += (double)xv * b.w;
    }
#pragma unroll
    for (int j = 0; j < NE; j++)
#pragma unroll
        for (int s = 16; s > 0; s >>= 1)
            acc[j] += __shfl_xor_sync(0xffffffffu, acc[j], s);
    if (lane == 0) {
        double m = acc[0]; int am = 0;
#pragma unroll
        for (int j = 1; j < NE; j++) if (acc[j] > m) { m = acc[j]; am = j; }
        double s = 0.0;
#pragma unroll
        for (int j = 0; j < NE; j++) s += exp(acc[j] - m);
        g_scale[warp] = (float)(1.0 / s);
        int pos = atomicAdd(&g_count[am], 1);
        g_slot[am * T_TOK + pos] = warp;
    }
}

// ---------------- elementwise hi/lo split; targets selected IN-KERNEL -------
template <int SEL>   // 0: x planes, 1: w1 planes, 2: w2 planes
__global__ void split_sel_k(const float* __restrict__ in) {
    __nv_bfloat16* hi = (SEL == 0) ? g_x_hi : (SEL == 1) ? g_w1_hi : g_w2_hi;
    __nv_bfloat16* lo = (SEL == 0) ? g_x_lo : (SEL == 1) ? g_w1_lo : g_w2_lo;
    size_t i = (size_t)blockIdx.x * blockDim.x + threadIdx.x;
    float4 v = reinterpret_cast<const float4*>(in)[i];
    float f[4] = {v.x, v.y, v.z, v.w}, l[4];
#pragma unroll
    for (int q = 0; q < 4; q++) {
        float h = __bfloat162float(__float2bfloat16_rn(f[q]));
        l[q] = f[q] - h;
    }
    reinterpret_cast<uint2*>(hi)[i] = make_uint2(pack_bf2(f[0], f[1]), pack_bf2(f[2], f[3]));
    reinterpret_cast<uint2*>(lo)[i] = make_uint2(pack_bf2(l[0], l[1]), pack_bf2(l[2], l[3]));
}

// ---------------- grouped GEMM: raw mma, double-buffered smem ---------------
// Block 128x128, k-step 16, 8 warps (wm = wid&1, wn = wid>>1). R7 fragment math.
// Two 16 KB stages. One sync/k-step; STS to stage s^1 overlaps MMA on stage s.
// MMA issue order: split-term OUTERMOST (hh, hl, lh) -> 16 independent
// accumulators between successive writes to the same acc (no exposed RAW).
// Per-accumulator FP order unchanged (hh then hl then lh).
// A swizzle: chunk c ^= (row>>2)&1.  B swizzle: n-chunk nc ^= krow&7.
template <bool DO_GELU>
__global__ __launch_bounds__(256, 2)
void moe_mma(const float* __restrict__ Bias, float* __restrict__ OutF,
             int K, int N) {
    const int e  = blockIdx.z;
    const int Me = g_count[e];
    const int m0 = blockIdx.y * 128;
    if (m0 >= Me) return;
    const int n0 = blockIdx.x * 128;

    const __nv_bfloat16* Ahi = DO_GELU ? g_x_hi : g_h_hi;
    const __nv_bfloat16* Alo = DO_GELU ? g_x_lo : g_h_lo;
    const __nv_bfloat16* Whi = DO_GELU ? g_w1_hi : g_w2_hi;
    const __nv_bfloat16* Wlo = DO_GELU ? g_w1_lo : g_w2_lo;

    __shared__ __align__(16) unsigned char sm[2][16384];
    __shared__ int toks[128];

    const int tid = threadIdx.x;
    if (tid < 128) {
        int p = m0 + tid;
        toks[tid] = (p < Me) ? g_slot[e * T_TOK + p] : -1;
    }
    __syncthreads();

    // A staging: thread -> (row ar, 16B chunk ac8 of the 32B row)
    const int ar  = tid >> 1;
    const int ac8 = tid & 1;
    const int tokA = toks[ar];
    const __nv_bfloat16* aph = (tokA >= 0) ? (Ahi + (size_t)tokA * K + ac8 * 8) : nullptr;
    const __nv_bfloat16* apl = (tokA >= 0) ? (Alo + (size_t)tokA * K + ac8 * 8) : nullptr;
    const unsigned aoff = (unsigned)(ar * 32 + ((ac8 ^ ((ar >> 2) & 1)) << 4));
    // B staging: thread -> (k-row bk, n-chunk bnc)
    const int bk  = tid >> 4;
    const int bnc = tid & 15;
    const size_t bbase = ((size_t)e * K + bk) * N + n0 + bnc * 8;
    const unsigned boff = (unsigned)(bk * 256 + ((bnc ^ (bk & 7)) << 4));

    const int wid = tid >> 5, lane = tid & 31;
    const int wm = wid & 1, wn = wid >> 1;
    const int lane4 = lane & 15, laneh = lane >> 4;
    const unsigned offA = (unsigned)((wm * 64 + lane4) * 32 + ((laneh ^ ((lane4 >> 2) & 1)) << 4));
    const int khalf = (lane >> 4) & 1, ngrp = (lane >> 3) & 1, tt = lane & 7;
    const int krow = khalf * 8 + tt;
    const unsigned offB0 = (unsigned)(8192 + krow * 256 + (((wn * 4 + ngrp)     ^ (krow & 7)) << 4));
    const unsigned offB1 = (unsigned)(8192 + krow * 256 + (((wn * 4 + 2 + ngrp) ^ (krow & 7)) << 4));
    const unsigned base = smem_u32(sm);

    float acc[4][4][4];
#pragma unroll
    for (int i = 0; i < 4; i++)
#pragma unroll
        for (int j = 0; j < 4; j++)
#pragma unroll
            for (int q = 0; q < 4; q++) acc[i][j][q] = 0.0f;

    // prologue: k0 regs -> stage 0 -> sync
    uint4 pah = make_uint4(0u, 0u, 0u, 0u), pal = pah;
    if (aph) {
        pah = *reinterpret_cast<const uint4*>(aph);
        pal = *reinterpret_cast<const uint4*>(apl);
    }
    uint4 pbh = *reinterpret_cast<const uint4*>(Whi + bbase);
    uint4 pbl = *reinterpret_cast<const uint4*>(Wlo + bbase);
    {
        unsigned char* s0 = (unsigned char*)sm;
        *reinterpret_cast<uint4*>(s0 + aoff)          = pah;
        *reinterpret_cast<uint4*>(s0 + 4096  + aoff)  = pal;
        *reinterpret_cast<uint4*>(s0 + 8192  + boff)  = pbh;
        *reinterpret_cast<uint4*>(s0 + 12288 + boff)  = pbl;
    }
    __syncthreads();

    const int KS = K / 16;
    for (int i = 0; i < KS; i++) {
        const int k1 = (i + 1) * 16;
        // issue next-stage LDGs early (land while MMA runs)
        if (k1 < K) {
            if (aph) {
                pah = *reinterpret_cast<const uint4*>(aph + k1);
                pal = *reinterpret_cast<const uint4*>(apl + k1);
            }
            pbh = *reinterpret_cast<const uint4*>(Whi + bbase + (size_t)k1 * N);
            pbl = *reinterpret_cast<const uint4*>(Wlo + bbase + (size_t)k1 * N);
        }

        const unsigned sb = base + (i & 1) * 16384;
        unsigned ah[4][4], al[4][4], bh[2][4], bl[2][4];
#pragma unroll
        for (int mi = 0; mi < 4; mi++) {
            LDSM_X4(ah[mi], sb + offA + mi * 512);
            LDSM_X4(al[mi], sb + 4096 + offA + mi * 512);
        }
        LDSM_X4_T(bh[0], sb + offB0);
        LDSM_X4_T(bh[1], sb + offB1);
        LDSM_X4_T(bl[0], sb + offB0 + 4096);
        LDSM_X4_T(bl[1], sb + offB1 + 4096);

        // term-outermost MMA order: no back-to-back RAW on any accumulator
#pragma unroll
        for (int mi = 0; mi < 4; mi++)
#pragma unroll
            for (int nt = 0; nt < 4; nt++) {
                const int nj = nt >> 1, sel = nt & 1;
                MMA_BF16(acc[mi][nt], ah[mi], bh[nj][sel], bh[nj][sel + 2]);
            }
#pragma unroll
        for (int mi = 0; mi < 4; mi++)
#pragma unroll
            for (int nt = 0; nt < 4; nt++) {
                const int nj = nt >> 1, sel = nt & 1;
                MMA_BF16(acc[mi][nt], ah[mi], bl[nj][sel], bl[nj][sel + 2]);
            }
#pragma unroll
        for (int mi = 0; mi < 4; mi++)
#pragma unroll
            for (int nt = 0; nt < 4; nt++) {
                const int nj = nt >> 1, sel = nt & 1;
                MMA_BF16(acc[mi][nt], al[mi], bh[nj][sel], bh[nj][sel + 2]);
            }

        // store next stage (other buffer — no hazard with this stage's LDSMs)
        if (k1 < K) {
            unsigned char* sn = (unsigned char*)sm + ((i + 1) & 1) * 16384;
            *reinterpret_cast<uint4*>(sn + aoff)          = pah;
            *reinterpret_cast<uint4*>(sn + 4096  + aoff)  = pal;
            *reinterpret_cast<uint4*>(sn + 8192  + boff)  = pbh;
            *reinterpret_cast<uint4*>(sn + 12288 + boff)  = pbl;
        }
        __syncthreads();
    }

    // ---------------- epilogue (R7 mapping) ----------------
    // acc[mi][nt]: d0=(r0,c), d1=(r0,c+1), d2=(r0+8,c), d3=(r0+8,c+1)
    float bb[4][2];
#pragma unroll
    for (int nt = 0; nt < 4; nt++) {
        const float2 bv = *reinterpret_cast<const float2*>(
            Bias + (size_t)e * N + n0 + wn * 32 + nt * 8 + (lane & 3) * 2);
        bb[nt][0] = bv.x; bb[nt][1] = bv.y;
    }

#pragma unroll
    for (int mi = 0; mi < 4; mi++) {
        const int r0 = wm * 64 + mi * 16 + (lane >> 2);
        const int t0 = toks[r0], t1 = toks[r0 + 8];
        if (DO_GELU) {
#pragma unroll
            for (int nt = 0; nt < 4; nt++) {
                const int col = n0 + wn * 32 + nt * 8 + (lane & 3) * 2;
                if (t0 >= 0) {
                    float v0 = gelu_exact(acc[mi][nt][0] + bb[nt][0]);
                    float v1 = gelu_exact(acc[mi][nt][1] + bb[nt][1]);
                    float h0 = __bfloat162float(__float2bfloat16_rn(v0));
                    float h1 = __bfloat162float(__float2bfloat16_rn(v1));
                    *reinterpret_cast<unsigned*>(g_h_hi + (size_t)t0 * N + col) = pack_bf2(v0, v1);
                    *reinterpret_cast<unsigned*>(g_h_lo + (size_t)t0 * N + col) = pack_bf2(v0 - h0, v1 - h1);
                }
                if (t1 >= 0) {
                    float v2 = gelu_exact(acc[mi][nt][2] + bb[nt][0]);
                    float v3 = gelu_exact(acc[mi][nt][3] + bb[nt][1]);
                    float h2 = __bfloat162float(__float2bfloat16_rn(v2));
                    float h3 = __bfloat162float(__float2bfloat16_rn(v3));
                    *reinterpret_cast<unsigned*>(g_h_hi + (size_t)t1 * N + col) = pack_bf2(v2, v3);
                    *reinterpret_cast<unsigned*>(g_h_lo + (size_t)t1 * N + col) = pack_bf2(v2 - h2, v3 - h3);
                }
            }
        } else {
            const float s0 = (t0 >= 0) ? g_scale[t0] : 0.0f;
            const float s1 = (t1 >= 0) ? g_scale[t1] : 0.0f;
#pragma unroll
            for (int nt = 0; nt < 4; nt++) {
                const int col = n0 + wn * 32 + nt * 8 + (lane & 3) * 2;
                if (t0 >= 0) {
                    float2 v = make_float2((acc[mi][nt][0] + bb[nt][0]) * s0,
                                           (acc[mi][nt][1] + bb[nt][1]) * s0);
                    *reinterpret_cast<float2*>(OutF + (size_t)t0 * N + col) = v;
                }
                if (t1 >= 0) {
                    float2 v = make_float2((acc[mi][nt][2] + bb[nt][0]) * s1,
                                           (acc[mi][nt][3] + bb[nt][1]) * s1);
                    *reinterpret_cast<float2*>(OutF + (size_t)t1 * N + col) = v;
                }
            }
        }
    }
}

// ---------------- launch ----------------
extern "C" void kernel_launch(void* const* d_in, const int* in_sizes, int n_in,
                              void* d_out, int out_size) {
    const float* x  = (const float*)d_in[0];
    const float* gw = (const float*)d_in[1];
    const float* w1 = (const float*)d_in[2];
    const float* b1 = (const float*)d_in[3];
    const float* w2 = (const float*)d_in[4];
    const float* b2 = (const float*)d_in[5];
    float* out = (float*)d_out;

    zero_counts_k<<<1, 32>>>();
    router_k<<<(T_TOK * 32) / 256, 256>>>(x, gw);

    split_sel_k<0><<<((size_t)T_TOK * D_IN / 4) / 256, 256>>>(x);
    split_sel_k<1><<<((size_t)NE * D_IN * DFF / 4) / 256, 256>>>(w1);
    split_sel_k<2><<<((size_t)NE * DFF * D_IN / 4) / 256, 256>>>(w2);

    dim3 g1(DFF / 128, T_TOK / 128, NE);   // empty m-tiles early-exit
    moe_mma<true><<<g1, 256>>>(b1, nullptr, D_IN, DFF);

    dim3 g2(D_IN / 128, T_TOK / 128, NE);
    moe_mma<false><<<g2, 256>>>(b2, out, DFF, D_IN);
}

// round 15
// speedup vs baseline: 1.8836x; 1.3007x over previous
#include <cuda_runtime.h>
#include <cuda_fp16.h>
#include <math.h>
#include <cstdint>
#include <cstddef>

#define T_TOK 8192
#define D_IN  1024
#define DFF   4096
#define NE    8

// ---------------- device scratch (ONLY referenced inside kernels) -----------
__device__ int   g_count[NE];
__device__ int   g_slot[NE * T_TOK];
__device__ float g_scale[T_TOK];

__device__ __align__(16) __half g_x_f[(size_t)T_TOK * D_IN];        // fp16(x)
__device__ __align__(16) __half g_h_f[(size_t)T_TOK * DFF];         // fp16(h), token-indexed
__device__ __align__(16) __half g_w1_hi[(size_t)NE * D_IN * DFF];   // [E][K][N] native
__device__ __align__(16) __half g_w1_lo[(size_t)NE * D_IN * DFF];
__device__ __align__(16) __half g_w2_hi[(size_t)NE * DFF * D_IN];
__device__ __align__(16) __half g_w2_lo[(size_t)NE * DFF * D_IN];

// ---------------- PTX helpers ----------------
__device__ __forceinline__ unsigned smem_u32(const void* p) {
    unsigned a;
    asm("{ .reg .u64 t; cvta.to.shared.u64 t, %1; cvt.u32.u64 %0, t; }" : "=r"(a) : "l"(p));
    return a;
}
#define LDSM_X4(r, a) \
    asm volatile("ldmatrix.sync.aligned.m8n8.x4.shared.b16 {%0,%1,%2,%3}, [%4];" \
        : "=r"((r)[0]), "=r"((r)[1]), "=r"((r)[2]), "=r"((r)[3]) : "r"(a))
#define LDSM_X4_T(r, a) \
    asm volatile("ldmatrix.sync.aligned.m8n8.x4.trans.shared.b16 {%0,%1,%2,%3}, [%4];" \
        : "=r"((r)[0]), "=r"((r)[1]), "=r"((r)[2]), "=r"((r)[3]) : "r"(a))
#define MMA_F16(d, a, b0, b1) \
    asm volatile("mma.sync.aligned.m16n8k16.row.col.f32.f16.f16.f32 " \
        "{%0,%1,%2,%3}, {%4,%5,%6,%7}, {%8,%9}, {%0,%1,%2,%3};" \
        : "+f"((d)[0]), "+f"((d)[1]), "+f"((d)[2]), "+f"((d)[3]) \
        : "r"((a)[0]), "r"((a)[1]), "r"((a)[2]), "r"((a)[3]), "r"(b0), "r"(b1))

// ---------------- misc helpers ----------------
__device__ __forceinline__ float gelu_exact(float v) {
    return 0.5f * v * (1.0f + erff(v * 0.70710678118654752f));
}
__device__ __forceinline__ unsigned pack_h2(float a, float b) {
    __half2 t = __floats2half2_rn(a, b);
    return reinterpret_cast<unsigned&>(t);
}

// ---------------- kernel 0: zero counters ----------------
__global__ void zero_counts_k() { if (threadIdx.x < NE) g_count[threadIdx.x] = 0; }

// ---------------- kernel 1: router (proven) ----------------
__global__ void router_k(const float* __restrict__ x, const float* __restrict__ gw) {
    int warp = (blockIdx.x * blockDim.x + threadIdx.x) >> 5;
    int lane = threadIdx.x & 31;
    if (warp >= T_TOK) return;
    const float* xr = x + (size_t)warp * D_IN;
    double acc[NE];
#pragma unroll
    for (int j = 0; j < NE; j++) acc[j] = 0.0;
    for (int d = lane; d < D_IN; d += 32) {
        float xv = xr[d];
        const float4* g4 = reinterpret_cast<const float4*>(gw + d * NE);
        float4 a = g4[0], b = g4[1];
        acc[0] += (double)xv * a.x; acc[1] += (double)xv * a.y;
        acc[2] += (double)xv * a.z; acc[3] += (double)xv * a.w;
        acc[4] += (double)xv * b.x; acc[5] += (double)xv * b.y;
        acc[6] += (double)xv * b.z; acc[7] += (double)xv * b.w;
    }
#pragma unroll
    for (int j = 0; j < NE; j++)
#pragma unroll
        for (int s = 16; s > 0; s >>= 1)
            acc[j] += __shfl_xor_sync(0xffffffffu, acc[j], s);
    if (lane == 0) {
        double m = acc[0]; int am = 0;
#pragma unroll
        for (int j = 1; j < NE; j++) if (acc[j] > m) { m = acc[j]; am = j; }
        double s = 0.0;
#pragma unroll
        for (int j = 0; j < NE; j++) s += exp(acc[j] - m);
        g_scale[warp] = (float)(1.0 / s);
        int pos = atomicAdd(&g_count[am], 1);
        g_slot[am * T_TOK + pos] = warp;
    }
}

// ---------------- conversion prepass; targets selected IN-KERNEL ------------
// SEL 0: x -> fp16 plane (no split).  SEL 1/2: w1/w2 -> fp16 hi + lo planes.
template <int SEL>
__global__ void conv_sel_k(const float* __restrict__ in) {
    size_t i = (size_t)blockIdx.x * blockDim.x + threadIdx.x;
    float4 v = reinterpret_cast<const float4*>(in)[i];
    if (SEL == 0) {
        reinterpret_cast<uint2*>(g_x_f)[i] =
            make_uint2(pack_h2(v.x, v.y), pack_h2(v.z, v.w));
    } else {
        __half* hi = (SEL == 1) ? g_w1_hi : g_w2_hi;
        __half* lo = (SEL == 1) ? g_w1_lo : g_w2_lo;
        float f[4] = {v.x, v.y, v.z, v.w}, l[4];
#pragma unroll
        for (int q = 0; q < 4; q++) {
            float h = __half2float(__float2half_rn(f[q]));
            l[q] = f[q] - h;
        }
        reinterpret_cast<uint2*>(hi)[i] = make_uint2(pack_h2(f[0], f[1]), pack_h2(f[2], f[3]));
        reinterpret_cast<uint2*>(lo)[i] = make_uint2(pack_h2(l[0], l[1]), pack_h2(l[2], l[3]));
    }
}

// ---------------- grouped GEMM: fp16 2-term, double-buffered smem -----------
// D = A_f16 @ (W_hi + W_lo).  Block 128x128, k-step 16, 8 warps.
// Stage (12 KB): A 4K | Bhi 4K | Blo 4K; two stages (24 KB static).
// One sync/k-step; STS to stage s^1 overlaps MMA on stage s (R11 schedule).
// A swizzle: chunk c ^= (row>>2)&1.  B swizzle: n-chunk nc ^= krow&7.
template <bool DO_GELU>
__global__ __launch_bounds__(256, 2)
void moe_mma(const float* __restrict__ Bias, float* __restrict__ OutF,
             int K, int N) {
    const int e  = blockIdx.z;
    const int Me = g_count[e];
    const int m0 = blockIdx.y * 128;
    if (m0 >= Me) return;
    const int n0 = blockIdx.x * 128;

    const __half* A   = DO_GELU ? g_x_f : g_h_f;
    const __half* Whi = DO_GELU ? g_w1_hi : g_w2_hi;
    const __half* Wlo = DO_GELU ? g_w1_lo : g_w2_lo;

    __shared__ __align__(16) unsigned char sm[2][12288];
    __shared__ int toks[128];

    const int tid = threadIdx.x;
    if (tid < 128) {
        int p = m0 + tid;
        toks[tid] = (p < Me) ? g_slot[e * T_TOK + p] : -1;
    }
    __syncthreads();

    // A staging: thread -> (row ar, 16B chunk ac8 of the 32B row)
    const int ar  = tid >> 1;
    const int ac8 = tid & 1;
    const int tokA = toks[ar];
    const __half* apt = (tokA >= 0) ? (A + (size_t)tokA * K + ac8 * 8) : nullptr;
    const unsigned aoff = (unsigned)(ar * 32 + ((ac8 ^ ((ar >> 2) & 1)) << 4));
    // B staging: thread -> (k-row bk, n-chunk bnc)
    const int bk  = tid >> 4;
    const int bnc = tid & 15;
    const size_t bbase = ((size_t)e * K + bk) * N + n0 + bnc * 8;
    const unsigned boff = (unsigned)(4096 + bk * 256 + ((bnc ^ (bk & 7)) << 4));

    const int wid = tid >> 5, lane = tid & 31;
    const int wm = wid & 1, wn = wid >> 1;
    const int lane4 = lane & 15, laneh = lane >> 4;
    const unsigned offA = (unsigned)((wm * 64 + lane4) * 32 + ((laneh ^ ((lane4 >> 2) & 1)) << 4));
    const int ngrp = (lane >> 3) & 1, tt = lane & 7;
    const int krow = ((lane >> 4) & 1) * 8 + tt;
    const unsigned offB0 = (unsigned)(4096 + krow * 256 + (((wn * 4 + ngrp)     ^ (krow & 7)) << 4));
    const unsigned offB1 = (unsigned)(4096 + krow * 256 + (((wn * 4 + 2 + ngrp) ^ (krow & 7)) << 4));
    const unsigned base = smem_u32(sm);

    float acc[4][4][4];
#pragma unroll
    for (int i = 0; i < 4; i++)
#pragma unroll
        for (int j = 0; j < 4; j++)
#pragma unroll
            for (int q = 0; q < 4; q++) acc[i][j][q] = 0.0f;

    // prologue: k0 regs -> stage 0 -> sync
    uint4 pa = make_uint4(0u, 0u, 0u, 0u);
    if (apt) pa = *reinterpret_cast<const uint4*>(apt);
    uint4 pbh = *reinterpret_cast<const uint4*>(Whi + bbase);
    uint4 pbl = *reinterpret_cast<const uint4*>(Wlo + bbase);
    {
        unsigned char* s0 = (unsigned char*)sm;
        *reinterpret_cast<uint4*>(s0 + aoff)         = pa;
        *reinterpret_cast<uint4*>(s0 + boff)         = pbh;
        *reinterpret_cast<uint4*>(s0 + 4096 + boff)  = pbl;
    }
    __syncthreads();

    const int KS = K / 16;
    for (int i = 0; i < KS; i++) {
        const int k1 = (i + 1) * 16;
        // issue next-stage LDGs early (land while MMA runs)
        if (k1 < K) {
            if (apt) pa = *reinterpret_cast<const uint4*>(apt + k1);
            pbh = *reinterpret_cast<const uint4*>(Whi + bbase + (size_t)k1 * N);
            pbl = *reinterpret_cast<const uint4*>(Wlo + bbase + (size_t)k1 * N);
        }

        const unsigned sb = base + (i & 1) * 12288;
        unsigned ah[4][4], bh[2][4], bl[2][4];
#pragma unroll
        for (int mi = 0; mi < 4; mi++)
            LDSM_X4(ah[mi], sb + offA + mi * 512);
        LDSM_X4_T(bh[0], sb + offB0);
        LDSM_X4_T(bh[1], sb + offB1);
        LDSM_X4_T(bl[0], sb + offB0 + 4096);
        LDSM_X4_T(bl[1], sb + offB1 + 4096);

#pragma unroll
        for (int mi = 0; mi < 4; mi++)
#pragma unroll
            for (int nt = 0; nt < 4; nt++) {
                const int nj = nt >> 1, sel = nt & 1;
                MMA_F16(acc[mi][nt], ah[mi], bh[nj][sel], bh[nj][sel + 2]);
                MMA_F16(acc[mi][nt], ah[mi], bl[nj][sel], bl[nj][sel + 2]);
            }

        // store next stage (other buffer — no hazard with this stage's LDSMs)
        if (k1 < K) {
            unsigned char* sn = (unsigned char*)sm + ((i + 1) & 1) * 12288;
            *reinterpret_cast<uint4*>(sn + aoff)         = pa;
            *reinterpret_cast<uint4*>(sn + boff)         = pbh;
            *reinterpret_cast<uint4*>(sn + 4096 + boff)  = pbl;
        }
        __syncthreads();
    }

    // ---------------- epilogue (R7 mapping) ----------------
    // acc[mi][nt]: d0=(r0,c), d1=(r0,c+1), d2=(r0+8,c), d3=(r0+8,c+1)
    float bb[4][2];
#pragma unroll
    for (int nt = 0; nt < 4; nt++) {
        const float2 bv = *reinterpret_cast<const float2*>(
            Bias + (size_t)e * N + n0 + wn * 32 + nt * 8 + (lane & 3) * 2);
        bb[nt][0] = bv.x; bb[nt][1] = bv.y;
    }

#pragma unroll
    for (int mi = 0; mi < 4; mi++) {
        const int r0 = wm * 64 + mi * 16 + (lane >> 2);
        const int t0 = toks[r0], t1 = toks[r0 + 8];
        if (DO_GELU) {
#pragma unroll
            for (int nt = 0; nt < 4; nt++) {
                const int col = n0 + wn * 32 + nt * 8 + (lane & 3) * 2;
                if (t0 >= 0) {
                    float v0 = gelu_exact(acc[mi][nt][0] + bb[nt][0]);
                    float v1 = gelu_exact(acc[mi][nt][1] + bb[nt][1]);
                    *reinterpret_cast<unsigned*>(g_h_f + (size_t)t0 * N + col) = pack_h2(v0, v1);
                }
                if (t1 >= 0) {
                    float v2 = gelu_exact(acc[mi][nt][2] + bb[nt][0]);
                    float v3 = gelu_exact(acc[mi][nt][3] + bb[nt][1]);
                    *reinterpret_cast<unsigned*>(g_h_f + (size_t)t1 * N + col) = pack_h2(v2, v3);
                }
            }
        } else {
            const float s0 = (t0 >= 0) ? g_scale[t0] : 0.0f;
            const float s1 = (t1 >= 0) ? g_scale[t1] : 0.0f;
#pragma unroll
            for (int nt = 0; nt < 4; nt++) {
                const int col = n0 + wn * 32 + nt * 8 + (lane & 3) * 2;
                if (t0 >= 0) {
                    float2 v = make_float2((acc[mi][nt][0] + bb[nt][0]) * s0,
                                           (acc[mi][nt][1] + bb[nt][1]) * s0);
                    *reinterpret_cast<float2*>(OutF + (size_t)t0 * N + col) = v;
                }
                if (t1 >= 0) {
                    float2 v = make_float2((acc[mi][nt][2] + bb[nt][0]) * s1,
                                           (acc[mi][nt][3] + bb[nt][1]) * s1);
                    *reinterpret_cast<float2*>(OutF + (size_t)t1 * N + col) = v;
                }
            }
        }
    }
}

// ---------------- launch ----------------
extern "C" void kernel_launch(void* const* d_in, const int* in_sizes, int n_in,
                              void* d_out, int out_size) {
    const float* x  = (const float*)d_in[0];
    const float* gw = (const float*)d_in[1];
    const float* w1 = (const float*)d_in[2];
    const float* b1 = (const float*)d_in[3];
    const float* w2 = (const float*)d_in[4];
    const float* b2 = (const float*)d_in[5];
    float* out = (float*)d_out;

    zero_counts_k<<<1, 32>>>();
    router_k<<<(T_TOK * 32) / 256, 256>>>(x, gw);

    conv_sel_k<0><<<((size_t)T_TOK * D_IN / 4) / 256, 256>>>(x);
    conv_sel_k<1><<<((size_t)NE * D_IN * DFF / 4) / 256, 256>>>(w1);
    conv_sel_k<2><<<((size_t)NE * DFF * D_IN / 4) / 256, 256>>>(w2);

    dim3 g1(DFF / 128, T_TOK / 128, NE);   // empty m-tiles early-exit
    moe_mma<true><<<g1, 256>>>(b1, nullptr, D_IN, DFF);

    dim3 g2(D_IN / 128, T_TOK / 128, NE);
    moe_mma<false><<<g2, 256>>>(b2, out, DFF, D_IN);
}

// round 16
// speedup vs baseline: 2.2549x; 1.1971x over previous
#include <cuda_runtime.h>
#include <cuda_fp16.h>
#include <math.h>
#include <cstdint>
#include <cstddef>

#define T_TOK 8192
#define D_IN  1024
#define DFF   4096
#define NE    8

// ---------------- device scratch (ONLY referenced inside kernels) -----------
__device__ int   g_count[NE];
__device__ int   g_slot[NE * T_TOK];
__device__ float g_scale[T_TOK];

__device__ __align__(16) __half g_x_f[(size_t)T_TOK * D_IN];       // fp16(x)
__device__ __align__(16) __half g_h_f[(size_t)T_TOK * DFF];        // fp16(h), token-indexed
__device__ __align__(16) __half g_w1_f[(size_t)NE * D_IN * DFF];   // fp16(w1), [E][K][N]
__device__ __align__(16) __half g_w2_f[(size_t)NE * DFF * D_IN];   // fp16(w2), [E][K][N]

// ---------------- PTX helpers ----------------
__device__ __forceinline__ unsigned smem_u32(const void* p) {
    unsigned a;
    asm("{ .reg .u64 t; cvta.to.shared.u64 t, %1; cvt.u32.u64 %0, t; }" : "=r"(a) : "l"(p));
    return a;
}
#define LDSM_X4(r, a) \
    asm volatile("ldmatrix.sync.aligned.m8n8.x4.shared.b16 {%0,%1,%2,%3}, [%4];" \
        : "=r"((r)[0]), "=r"((r)[1]), "=r"((r)[2]), "=r"((r)[3]) : "r"(a))
#define LDSM_X4_T(r, a) \
    asm volatile("ldmatrix.sync.aligned.m8n8.x4.trans.shared.b16 {%0,%1,%2,%3}, [%4];" \
        : "=r"((r)[0]), "=r"((r)[1]), "=r"((r)[2]), "=r"((r)[3]) : "r"(a))
#define MMA_F16(d, a, b0, b1) \
    asm volatile("mma.sync.aligned.m16n8k16.row.col.f32.f16.f16.f32 " \
        "{%0,%1,%2,%3}, {%4,%5,%6,%7}, {%8,%9}, {%0,%1,%2,%3};" \
        : "+f"((d)[0]), "+f"((d)[1]), "+f"((d)[2]), "+f"((d)[3]) \
        : "r"((a)[0]), "r"((a)[1]), "r"((a)[2]), "r"((a)[3]), "r"(b0), "r"(b1))

// ---------------- misc helpers ----------------
__device__ __forceinline__ float gelu_exact(float v) {
    return 0.5f * v * (1.0f + erff(v * 0.70710678118654752f));
}
__device__ __forceinline__ unsigned pack_h2(float a, float b) {
    __half2 t = __floats2half2_rn(a, b);
    return reinterpret_cast<unsigned&>(t);
}

// ---------------- kernel 0: zero counters ----------------
__global__ void zero_counts_k() { if (threadIdx.x < NE) g_count[threadIdx.x] = 0; }

// ---------------- kernel 1: router (proven) ----------------
__global__ void router_k(const float* __restrict__ x, const float* __restrict__ gw) {
    int warp = (blockIdx.x * blockDim.x + threadIdx.x) >> 5;
    int lane = threadIdx.x & 31;
    if (warp >= T_TOK) return;
    const float* xr = x + (size_t)warp * D_IN;
    double acc[NE];
#pragma unroll
    for (int j = 0; j < NE; j++) acc[j] = 0.0;
    for (int d = lane; d < D_IN; d += 32) {
        float xv = xr[d];
        const float4* g4 = reinterpret_cast<const float4*>(gw + d * NE);
        float4 a = g4[0], b = g4[1];
        acc[0] += (double)xv * a.x; acc[1] += (double)xv * a.y;
        acc[2] += (double)xv * a.z; acc[3] += (double)xv * a.w;
        acc[4] += (double)xv * b.x; acc[5] += (double)xv * b.y;
        acc[6] += (double)xv * b.z; acc[7] += (double)xv * b.w;
    }
#pragma unroll
    for (int j = 0; j < NE; j++)
#pragma unroll
        for (int s = 16; s > 0; s >>= 1)
            acc[j] += __shfl_xor_sync(0xffffffffu, acc[j], s);
    if (lane == 0) {
        double m = acc[0]; int am = 0;
#pragma unroll
        for (int j = 1; j < NE; j++) if (acc[j] > m) { m = acc[j]; am = j; }
        double s = 0.0;
#pragma unroll
        for (int j = 0; j < NE; j++) s += exp(acc[j] - m);
        g_scale[warp] = (float)(1.0 / s);
        int pos = atomicAdd(&g_count[am], 1);
        g_slot[am * T_TOK + pos] = warp;
    }
}

// ---------------- fp16 conversion prepass; target selected IN-KERNEL --------
template <int SEL>   // 0: x, 1: w1, 2: w2
__global__ void conv_sel_k(const float* __restrict__ in) {
    __half* dst = (SEL == 0) ? g_x_f : (SEL == 1) ? g_w1_f : g_w2_f;
    size_t i = (size_t)blockIdx.x * blockDim.x + threadIdx.x;
    float4 v = reinterpret_cast<const float4*>(in)[i];
    reinterpret_cast<uint2*>(dst)[i] = make_uint2(pack_h2(v.x, v.y), pack_h2(v.z, v.w));
}

// ---------------- grouped GEMM: fp16 1-term, double-buffered smem -----------
// D = A_f16 @ W_f16 (fp32 accumulate). Block 128x128, k-step 16, 8 warps.
// Stage (8 KB): A 4K | B 4K; two stages (16 KB static). One sync/k-step;
// STS to stage s^1 overlaps MMA on stage s (R11 schedule).
// A swizzle: chunk c ^= (row>>2)&1.  B swizzle: n-chunk nc ^= krow&7.
template <bool DO_GELU>
__global__ __launch_bounds__(256, 2)
void moe_mma(const float* __restrict__ Bias, float* __restrict__ OutF,
             int K, int N) {
    const int e  = blockIdx.z;
    const int Me = g_count[e];
    const int m0 = blockIdx.y * 128;
    if (m0 >= Me) return;
    const int n0 = blockIdx.x * 128;

    const __half* A = DO_GELU ? g_x_f : g_h_f;
    const __half* W = DO_GELU ? g_w1_f : g_w2_f;

    __shared__ __align__(16) unsigned char sm[2][8192];
    __shared__ int toks[128];

    const int tid = threadIdx.x;
    if (tid < 128) {
        int p = m0 + tid;
        toks[tid] = (p < Me) ? g_slot[e * T_TOK + p] : -1;
    }
    __syncthreads();

    // A staging: thread -> (row ar, 16B chunk ac8 of the 32B row)
    const int ar  = tid >> 1;
    const int ac8 = tid & 1;
    const int tokA = toks[ar];
    const __half* apt = (tokA >= 0) ? (A + (size_t)tokA * K + ac8 * 8) : nullptr;
    const unsigned aoff = (unsigned)(ar * 32 + ((ac8 ^ ((ar >> 2) & 1)) << 4));
    // B staging: thread -> (k-row bk, n-chunk bnc)
    const int bk  = tid >> 4;
    const int bnc = tid & 15;
    const size_t bbase = ((size_t)e * K + bk) * N + n0 + bnc * 8;
    const unsigned boff = (unsigned)(4096 + bk * 256 + ((bnc ^ (bk & 7)) << 4));

    const int wid = tid >> 5, lane = tid & 31;
    const int wm = wid & 1, wn = wid >> 1;
    const int lane4 = lane & 15, laneh = lane >> 4;
    const unsigned offA = (unsigned)((wm * 64 + lane4) * 32 + ((laneh ^ ((lane4 >> 2) & 1)) << 4));
    const int ngrp = (lane >> 3) & 1, tt = lane & 7;
    const int krow = ((lane >> 4) & 1) * 8 + tt;
    const unsigned offB0 = (unsigned)(4096 + krow * 256 + (((wn * 4 + ngrp)     ^ (krow & 7)) << 4));
    const unsigned offB1 = (unsigned)(4096 + krow * 256 + (((wn * 4 + 2 + ngrp) ^ (krow & 7)) << 4));
    const unsigned base = smem_u32(sm);

    float acc[4][4][4];
#pragma unroll
    for (int i = 0; i < 4; i++)
#pragma unroll
        for (int j = 0; j < 4; j++)
#pragma unroll
            for (int q = 0; q < 4; q++) acc[i][j][q] = 0.0f;

    // prologue: k0 regs -> stage 0 -> sync
    uint4 pa = make_uint4(0u, 0u, 0u, 0u);
    if (apt) pa = *reinterpret_cast<const uint4*>(apt);
    uint4 pb = *reinterpret_cast<const uint4*>(W + bbase);
    {
        unsigned char* s0 = (unsigned char*)sm;
        *reinterpret_cast<uint4*>(s0 + aoff) = pa;
        *reinterpret_cast<uint4*>(s0 + boff) = pb;
    }
    __syncthreads();

    const int KS = K / 16;
    for (int i = 0; i < KS; i++) {
        const int k1 = (i + 1) * 16;
        // issue next-stage LDGs early (land while MMA runs)
        if (k1 < K) {
            if (apt) pa = *reinterpret_cast<const uint4*>(apt + k1);
            pb = *reinterpret_cast<const uint4*>(W + bbase + (size_t)k1 * N);
        }

        const unsigned sb = base + (i & 1) * 8192;
        unsigned ah[4][4], bh[2][4];
#pragma unroll
        for (int mi = 0; mi < 4; mi++)
            LDSM_X4(ah[mi], sb + offA + mi * 512);
        LDSM_X4_T(bh[0], sb + offB0);
        LDSM_X4_T(bh[1], sb + offB1);

#pragma unroll
        for (int mi = 0; mi < 4; mi++)
#pragma unroll
            for (int nt = 0; nt < 4; nt++) {
                const int nj = nt >> 1, sel = nt & 1;
                MMA_F16(acc[mi][nt], ah[mi], bh[nj][sel], bh[nj][sel + 2]);
            }

        // store next stage (other buffer — no hazard with this stage's LDSMs)
        if (k1 < K) {
            unsigned char* sn = (unsigned char*)sm + ((i + 1) & 1) * 8192;
            *reinterpret_cast<uint4*>(sn + aoff) = pa;
            *reinterpret_cast<uint4*>(sn + boff) = pb;
        }
        __syncthreads();
    }

    // ---------------- epilogue (R7 mapping) ----------------
    // acc[mi][nt]: d0=(r0,c), d1=(r0,c+1), d2=(r0+8,c), d3=(r0+8,c+1)
    float bb[4][2];
#pragma unroll
    for (int nt = 0; nt < 4; nt++) {
        const float2 bv = *reinterpret_cast<const float2*>(
            Bias + (size_t)e * N + n0 + wn * 32 + nt * 8 + (lane & 3) * 2);
        bb[nt][0] = bv.x; bb[nt][1] = bv.y;
    }

#pragma unroll
    for (int mi = 0; mi < 4; mi++) {
        const int r0 = wm * 64 + mi * 16 + (lane >> 2);
        const int t0 = toks[r0], t1 = toks[r0 + 8];
        if (DO_GELU) {
#pragma unroll
            for (int nt = 0; nt < 4; nt++) {
                const int col = n0 + wn * 32 + nt * 8 + (lane & 3) * 2;
                if (t0 >= 0) {
                    float v0 = gelu_exact(acc[mi][nt][0] + bb[nt][0]);
                    float v1 = gelu_exact(acc[mi][nt][1] + bb[nt][1]);
                    *reinterpret_cast<unsigned*>(g_h_f + (size_t)t0 * N + col) = pack_h2(v0, v1);
                }
                if (t1 >= 0) {
                    float v2 = gelu_exact(acc[mi][nt][2] + bb[nt][0]);
                    float v3 = gelu_exact(acc[mi][nt][3] + bb[nt][1]);
                    *reinterpret_cast<unsigned*>(g_h_f + (size_t)t1 * N + col) = pack_h2(v2, v3);
                }
            }
        } else {
            const float s0 = (t0 >= 0) ? g_scale[t0] : 0.0f;
            const float s1 = (t1 >= 0) ? g_scale[t1] : 0.0f;
#pragma unroll
            for (int nt = 0; nt < 4; nt++) {
                const int col = n0 + wn * 32 + nt * 8 + (lane & 3) * 2;
                if (t0 >= 0) {
                    float2 v = make_float2((acc[mi][nt][0] + bb[nt][0]) * s0,
                                           (acc[mi][nt][1] + bb[nt][1]) * s0);
                    *reinterpret_cast<float2*>(OutF + (size_t)t0 * N + col) = v;
                }
                if (t1 >= 0) {
                    float2 v = make_float2((acc[mi][nt][2] + bb[nt][0]) * s1,
                                           (acc[mi][nt][3] + bb[nt][1]) * s1);
                    *reinterpret_cast<float2*>(OutF + (size_t)t1 * N + col) = v;
                }
            }
        }
    }
}

// ---------------- launch ----------------
extern "C" void kernel_launch(void* const* d_in, const int* in_sizes, int n_in,
                              void* d_out, int out_size) {
    const float* x  = (const float*)d_in[0];
    const float* gw = (const float*)d_in[1];
    const float* w1 = (const float*)d_in[2];
    const float* b1 = (const float*)d_in[3];
    const float* w2 = (const float*)d_in[4];
    const float* b2 = (const float*)d_in[5];
    float* out = (float*)d_out;

    zero_counts_k<<<1, 32>>>();
    router_k<<<(T_TOK * 32) / 256, 256>>>(x, gw);

    conv_sel_k<0><<<((size_t)T_TOK * D_IN / 4) / 256, 256>>>(x);
    conv_sel_k<1><<<((size_t)NE * D_IN * DFF / 4) / 256, 256>>>(w1);
    conv_sel_k<2><<<((size_t)NE * DFF * D_IN / 4) / 256, 256>>>(w2);

    dim3 g1(DFF / 128, T_TOK / 128, NE);   // empty m-tiles early-exit
    moe_mma<true><<<g1, 256>>>(b1, nullptr, D_IN, DFF);

    dim3 g2(D_IN / 128, T_TOK / 128, NE);
    moe_mma<false><<<g2, 256>>>(b2, out, DFF, D_IN);
}

// round 17
// speedup vs baseline: 2.5874x; 1.1475x over previous
#include <cuda_runtime.h>
#include <cuda_fp16.h>
#include <math.h>
#include <cstdint>
#include <cstddef>

#define T_TOK 8192
#define D_IN  1024
#define DFF   4096
#define NE    8

// ---------------- device scratch (ONLY referenced inside kernels) -----------
__device__ int   g_count[NE];
__device__ int   g_slot[NE * T_TOK];
__device__ float g_scale[T_TOK];

__device__ __align__(16) __half g_x_f[(size_t)T_TOK * D_IN];       // fp16(x)
__device__ __align__(16) __half g_h_f[(size_t)T_TOK * DFF];        // fp16(h), token-indexed
__device__ __align__(16) __half g_w1_f[(size_t)NE * D_IN * DFF];   // fp16(w1), [E][K][N]
__device__ __align__(16) __half g_w2_f[(size_t)NE * DFF * D_IN];   // fp16(w2), [E][K][N]

// ---------------- PTX helpers ----------------
__device__ __forceinline__ unsigned smem_u32(const void* p) {
    unsigned a;
    asm("{ .reg .u64 t; cvta.to.shared.u64 t, %1; cvt.u32.u64 %0, t; }" : "=r"(a) : "l"(p));
    return a;
}
#define LDSM_X4(r, a) \
    asm volatile("ldmatrix.sync.aligned.m8n8.x4.shared.b16 {%0,%1,%2,%3}, [%4];" \
        : "=r"((r)[0]), "=r"((r)[1]), "=r"((r)[2]), "=r"((r)[3]) : "r"(a))
#define LDSM_X4_T(r, a) \
    asm volatile("ldmatrix.sync.aligned.m8n8.x4.trans.shared.b16 {%0,%1,%2,%3}, [%4];" \
        : "=r"((r)[0]), "=r"((r)[1]), "=r"((r)[2]), "=r"((r)[3]) : "r"(a))
#define MMA_F16(d, a, b0, b1) \
    asm volatile("mma.sync.aligned.m16n8k16.row.col.f32.f16.f16.f32 " \
        "{%0,%1,%2,%3}, {%4,%5,%6,%7}, {%8,%9}, {%0,%1,%2,%3};" \
        : "+f"((d)[0]), "+f"((d)[1]), "+f"((d)[2]), "+f"((d)[3]) \
        : "r"((a)[0]), "r"((a)[1]), "r"((a)[2]), "r"((a)[3]), "r"(b0), "r"(b1))

// ---------------- misc helpers ----------------
__device__ __forceinline__ float gelu_exact(float v) {
    return 0.5f * v * (1.0f + erff(v * 0.70710678118654752f));
}
__device__ __forceinline__ unsigned pack_h2(float a, float b) {
    __half2 t = __floats2half2_rn(a, b);
    return reinterpret_cast<unsigned&>(t);
}

// ---------------- kernel 0: zero counters ----------------
__global__ void zero_counts_k() { if (threadIdx.x < NE) g_count[threadIdx.x] = 0; }

// ---------------- kernel 1: router (proven) ----------------
__global__ void router_k(const float* __restrict__ x, const float* __restrict__ gw) {
    int warp = (blockIdx.x * blockDim.x + threadIdx.x) >> 5;
    int lane = threadIdx.x & 31;
    if (warp >= T_TOK) return;
    const float* xr = x + (size_t)warp * D_IN;
    double acc[NE];
#pragma unroll
    for (int j = 0; j < NE; j++) acc[j] = 0.0;
    for (int d = lane; d < D_IN; d += 32) {
        float xv = xr[d];
        const float4* g4 = reinterpret_cast<const float4*>(gw + d * NE);
        float4 a = g4[0], b = g4[1];
        acc[0] += (double)xv * a.x; acc[1] += (double)xv * a.y;
        acc[2] += (double)xv * a.z; acc[3] += (double)xv * a.w;
        acc[4] += (double)xv * b.x; acc[5] += (double)xv * b.y;
        acc[6] += (double)xv * b.z; acc[7] += (double)xv * b.w;
    }
#pragma unroll
    for (int j = 0; j < NE; j++)
#pragma unroll
        for (int s = 16; s > 0; s >>= 1)
            acc[j] += __shfl_xor_sync(0xffffffffu, acc[j], s);
    if (lane == 0) {
        double m = acc[0]; int am = 0;
#pragma unroll
        for (int j = 1; j < NE; j++) if (acc[j] > m) { m = acc[j]; am = j; }
        double s = 0.0;
#pragma unroll
        for (int j = 0; j < NE; j++) s += exp(acc[j] - m);
        g_scale[warp] = (float)(1.0 / s);
        int pos = atomicAdd(&g_count[am], 1);
        g_slot[am * T_TOK + pos] = warp;
    }
}

// ---------------- fp16 conversion prepass; target selected IN-KERNEL --------
template <int SEL>   // 0: x, 1: w1, 2: w2
__global__ void conv_sel_k(const float* __restrict__ in) {
    __half* dst = (SEL == 0) ? g_x_f : (SEL == 1) ? g_w1_f : g_w2_f;
    size_t i = (size_t)blockIdx.x * blockDim.x + threadIdx.x;
    float4 v = reinterpret_cast<const float4*>(in)[i];
    reinterpret_cast<uint2*>(dst)[i] = make_uint2(pack_h2(v.x, v.y), pack_h2(v.z, v.w));
}

// ---------------- grouped GEMM: fp16 1-term, k-step 32, double buffer -------
// D = A_f16 @ W_f16 (fp32 accumulate). Block 128x128, 8 warps (2M x 4N).
// Stage (16 KB): A 8K (128 rows x 64B) | B 8K (32 krows x 256B); two stages.
// R12-proven layout: A 16B-chunk q at q ^ ((row>>1)&3); B n-chunk nc at nc ^ (krow&7).
// One sync per 32-k step: LDG next, LDSM/MMA kc0, LDSM/MMA kc1, STS next, sync.
template <bool DO_GELU>
__global__ __launch_bounds__(256, 2)
void moe_mma(const float* __restrict__ Bias, float* __restrict__ OutF,
             int K, int N) {
    const int e  = blockIdx.z;
    const int Me = g_count[e];
    const int m0 = blockIdx.y * 128;
    if (m0 >= Me) return;
    const int n0 = blockIdx.x * 128;

    const __half* A = DO_GELU ? g_x_f : g_h_f;
    const __half* W = DO_GELU ? g_w1_f : g_w2_f;

    __shared__ __align__(16) unsigned char sm[2][16384];
    __shared__ int toks[128];

    const int tid = threadIdx.x;
    if (tid < 128) {
        int p = m0 + tid;
        toks[tid] = (p < Me) ? g_slot[e * T_TOK + p] : -1;
    }
    __syncthreads();

    // A staging: thread -> (row ar, chunk 2h+aq per half h)
    const int ar = tid >> 1;
    const int aq = tid & 1;
    const int tokA = toks[ar];
    const __half* apt = (tokA >= 0) ? (A + (size_t)tokA * K + aq * 8) : nullptr;
    const int aswz = (ar >> 1) & 3;
    const unsigned aoff0 = (unsigned)(ar * 64 + (((0 + aq) ^ aswz) << 4));
    const unsigned aoff1 = (unsigned)(ar * 64 + (((2 + aq) ^ aswz) << 4));
    // B staging: thread -> (krow-in-half bk, n-chunk bnc); half h at +h*4096
    const int bk  = tid >> 4;
    const int bnc = tid & 15;
    const size_t bbase = ((size_t)e * K + bk) * N + n0 + bnc * 8;
    const unsigned boff = (unsigned)(8192 + bk * 256 + ((bnc ^ (bk & 7)) << 4));

    const int wid = tid >> 5, lane = tid & 31;
    const int wm = wid & 1, wn = wid >> 1;
    const int lane4 = lane & 15, laneh = lane >> 4;
    const int fswz = (lane4 >> 1) & 3;
    const unsigned offA0 = (unsigned)((wm * 64 + lane4) * 64 + (((0 + laneh) ^ fswz) << 4));
    const unsigned offA1 = (unsigned)((wm * 64 + lane4) * 64 + (((2 + laneh) ^ fswz) << 4));
    const int ngrp = (lane >> 3) & 1, tt = lane & 7;
    const int krow = ((lane >> 4) & 1) * 8 + tt;
    const unsigned offB0 = (unsigned)(8192 + krow * 256 + (((wn * 4 + ngrp)     ^ tt) << 4));
    const unsigned offB1 = (unsigned)(8192 + krow * 256 + (((wn * 4 + 2 + ngrp) ^ tt) << 4));
    const unsigned base = smem_u32(sm);

    float acc[4][4][4];
#pragma unroll
    for (int i = 0; i < 4; i++)
#pragma unroll
        for (int j = 0; j < 4; j++)
#pragma unroll
            for (int q = 0; q < 4; q++) acc[i][j][q] = 0.0f;

    // prologue: stage 0 <- k in [0, 32)
#pragma unroll
    for (int h = 0; h < 2; h++) {
        uint4 pa = make_uint4(0u, 0u, 0u, 0u);
        if (apt) pa = *reinterpret_cast<const uint4*>(apt + h * 16);
        uint4 pb = *reinterpret_cast<const uint4*>(W + bbase + (size_t)(h * 16) * N);
        *reinterpret_cast<uint4*>(sm[0] + ((h == 0) ? aoff0 : aoff1)) = pa;
        *reinterpret_cast<uint4*>(sm[0] + boff + h * 4096)            = pb;
    }
    __syncthreads();

    const int KS = K / 32;
    for (int i = 0; i < KS; i++) {
        const unsigned sb = base + (i & 1) * 16384;
        const bool more = (i + 1 < KS);
        const int kk = (i + 1) * 32;

        // LDG next step (both halves) — lands while this step's MMAs run
        uint4 pa0 = make_uint4(0u, 0u, 0u, 0u), pa1 = pa0, pb0, pb1;
        if (more) {
            if (apt) {
                pa0 = *reinterpret_cast<const uint4*>(apt + kk);
                pa1 = *reinterpret_cast<const uint4*>(apt + kk + 16);
            }
            pb0 = *reinterpret_cast<const uint4*>(W + bbase + (size_t)kk * N);
            pb1 = *reinterpret_cast<const uint4*>(W + bbase + (size_t)(kk + 16) * N);
        }

        unsigned ah[4][4], bh[2][4];
        // ---- kc = 0 ----
#pragma unroll
        for (int mi = 0; mi < 4; mi++)
            LDSM_X4(ah[mi], sb + offA0 + mi * 1024);
        LDSM_X4_T(bh[0], sb + offB0);
        LDSM_X4_T(bh[1], sb + offB1);
#pragma unroll
        for (int mi = 0; mi < 4; mi++)
#pragma unroll
            for (int nt = 0; nt < 4; nt++) {
                const int nj = nt >> 1, sel = nt & 1;
                MMA_F16(acc[mi][nt], ah[mi], bh[nj][sel], bh[nj][sel + 2]);
            }
        // ---- kc = 1 ----
#pragma unroll
        for (int mi = 0; mi < 4; mi++)
            LDSM_X4(ah[mi], sb + offA1 + mi * 1024);
        LDSM_X4_T(bh[0], sb + offB0 + 4096);
        LDSM_X4_T(bh[1], sb + offB1 + 4096);
#pragma unroll
        for (int mi = 0; mi < 4; mi++)
#pragma unroll
            for (int nt = 0; nt < 4; nt++) {
                const int nj = nt >> 1, sel = nt & 1;
                MMA_F16(acc[mi][nt], ah[mi], bh[nj][sel], bh[nj][sel + 2]);
            }

        // STS next stage (other buffer — no hazard with this stage's LDSMs)
        if (more) {
            unsigned char* sn = (unsigned char*)sm + ((i + 1) & 1) * 16384;
            *reinterpret_cast<uint4*>(sn + aoff0)        = pa0;
            *reinterpret_cast<uint4*>(sn + aoff1)        = pa1;
            *reinterpret_cast<uint4*>(sn + boff)         = pb0;
            *reinterpret_cast<uint4*>(sn + boff + 4096)  = pb1;
        }
        __syncthreads();
    }

    // ---------------- epilogue (R7 mapping) ----------------
    // acc[mi][nt]: d0=(r0,c), d1=(r0,c+1), d2=(r0+8,c), d3=(r0+8,c+1)
    float bb[4][2];
#pragma unroll
    for (int nt = 0; nt < 4; nt++) {
        const float2 bv = *reinterpret_cast<const float2*>(
            Bias + (size_t)e * N + n0 + wn * 32 + nt * 8 + (lane & 3) * 2);
        bb[nt][0] = bv.x; bb[nt][1] = bv.y;
    }

#pragma unroll
    for (int mi = 0; mi < 4; mi++) {
        const int r0 = wm * 64 + mi * 16 + (lane >> 2);
        const int t0 = toks[r0], t1 = toks[r0 + 8];
        if (DO_GELU) {
#pragma unroll
            for (int nt = 0; nt < 4; nt++) {
                const int col = n0 + wn * 32 + nt * 8 + (lane & 3) * 2;
                if (t0 >= 0) {
                    float v0 = gelu_exact(acc[mi][nt][0] + bb[nt][0]);
                    float v1 = gelu_exact(acc[mi][nt][1] + bb[nt][1]);
                    *reinterpret_cast<unsigned*>(g_h_f + (size_t)t0 * N + col) = pack_h2(v0, v1);
                }
                if (t1 >= 0) {
                    float v2 = gelu_exact(acc[mi][nt][2] + bb[nt][0]);
                    float v3 = gelu_exact(acc[mi][nt][3] + bb[nt][1]);
                    *reinterpret_cast<unsigned*>(g_h_f + (size_t)t1 * N + col) = pack_h2(v2, v3);
                }
            }
        } else {
            const float s0 = (t0 >= 0) ? g_scale[t0] : 0.0f;
            const float s1 = (t1 >= 0) ? g_scale[t1] : 0.0f;
#pragma unroll
            for (int nt = 0; nt < 4; nt++) {
                const int col = n0 + wn * 32 + nt * 8 + (lane & 3) * 2;
                if (t0 >= 0) {
                    float2 v = make_float2((acc[mi][nt][0] + bb[nt][0]) * s0,
                                           (acc[mi][nt][1] + bb[nt][1]) * s0);
                    *reinterpret_cast<float2*>(OutF + (size_t)t0 * N + col) = v;
                }
                if (t1 >= 0) {
                    float2 v = make_float2((acc[mi][nt][2] + bb[nt][0]) * s1,
                                           (acc[mi][nt][3] + bb[nt][1]) * s1);
                    *reinterpret_cast<float2*>(OutF + (size_t)t1 * N + col) = v;
                }
            }
        }
    }
}

// ---------------- launch ----------------
extern "C" void kernel_launch(void* const* d_in, const int* in_sizes, int n_in,
                              void* d_out, int out_size) {
    const float* x  = (const float*)d_in[0];
    const float* gw = (const float*)d_in[1];
    const float* w1 = (const float*)d_in[2];
    const float* b1 = (const float*)d_in[3];
    const float* w2 = (const float*)d_in[4];
    const float* b2 = (const float*)d_in[5];
    float* out = (float*)d_out;

    zero_counts_k<<<1, 32>>>();
    router_k<<<(T_TOK * 32) / 256, 256>>>(x, gw);

    conv_sel_k<0><<<((size_t)T_TOK * D_IN / 4) / 256, 256>>>(x);
    conv_sel_k<1><<<((size_t)NE * D_IN * DFF / 4) / 256, 256>>>(w1);
    conv_sel_k<2><<<((size_t)NE * DFF * D_IN / 4) / 256, 256>>>(w2);

    dim3 g1(DFF / 128, T_TOK / 128, NE);   // empty m-tiles early-exit
    moe_mma<true><<<g1, 256>>>(b1, nullptr, D_IN, DFF);

    dim3 g2(D_IN / 128, T_TOK / 128, NE);
    moe_mma<false><<<g2, 256>>>(b2, out, DFF, D_IN);
}